// round 9
// baseline (speedup 1.0000x reference)
#include <cuda_runtime.h>
#include <cstdint>
#include <math.h>

// Problem constants (B=4, S=1024, H=2048, I=2048, E=8, top_k=2)
#define TT   4096
#define HH   2048
#define EE   8
#define II   2048
#define I2   4096
#define NASS (TT * 2)
#define KDIM 2048
#define BM   128
#define BN   128
#define BK   64               // int8 bytes per chunk row
#define NCHUNK (KDIM / BK)    // 32
#define NSTAGE 3
#define TILEB (BM * BK)       // 8192 B per limb tile
#define STG   (4 * TILEB)     // 32768 B per stage (A0, A1, B0, B1)
#define SMEM_DYN (NSTAGE * STG)  // 98304 B

// swizzle of 16B segments within 64B rows: conflict-free for ldmatrix + cp.async
#define SWZ(r, cs) ((cs) ^ (((r) >> 1) & 3))

// ---------------- scratch (device globals) ----------------
__device__ int   g_topk_idx[TT * 2];
__device__ float g_topk_w[TT * 2];
__device__ int   g_cnt[EE];
__device__ int   g_off[EE];
__device__ int   g_cur[EE];
__device__ int   g_rowtok[NASS];
__device__ float g_roww[NASS];
// int8 limbs + per-row reciprocal scales (rs = rowmax/127; value = (l0 + l1/256)*rs)
__device__ int8_t g_xl0[(size_t)TT * HH],       g_xl1[(size_t)TT * HH];
__device__ float  g_xrs[TT];
__device__ int8_t g_w1l0[(size_t)EE * I2 * HH], g_w1l1[(size_t)EE * I2 * HH];
__device__ float  g_w1rs[EE * I2];
__device__ int8_t g_w2l0[(size_t)EE * HH * II], g_w2l1[(size_t)EE * HH * II];
__device__ float  g_w2rs[EE * HH];
__device__ float  g_actf[(size_t)NASS * II];    // fp32 activations (64 MB)
__device__ int8_t g_al0[(size_t)NASS * II],     g_al1[(size_t)NASS * II];
__device__ float  g_ars[NASS];

// ---------------- helpers ----------------
__device__ __forceinline__ uint32_t s2u(const void* p) {
    uint32_t a;
    asm("{ .reg .u64 t; cvta.to.shared.u64 t, %1; cvt.u32.u64 %0, t; }" : "=r"(a) : "l"(p));
    return a;
}
__device__ __forceinline__ void cpasync16(uint32_t dst, const void* src) {
    asm volatile("cp.async.cg.shared.global [%0], [%1], 16;" :: "r"(dst), "l"(src));
}
__device__ __forceinline__ void cp_commit() { asm volatile("cp.async.commit_group;"); }
template <int N>
__device__ __forceinline__ void cp_wait() { asm volatile("cp.async.wait_group %0;" :: "n"(N)); }

__device__ __forceinline__ void ldm_x4(uint32_t* r, uint32_t addr) {
    asm volatile("ldmatrix.sync.aligned.m8n8.x4.shared.b16 {%0,%1,%2,%3}, [%4];"
                 : "=r"(r[0]), "=r"(r[1]), "=r"(r[2]), "=r"(r[3]) : "r"(addr));
}
__device__ __forceinline__ void mma_s8(int* d, const uint32_t* a, uint32_t b0, uint32_t b1) {
    asm volatile("mma.sync.aligned.m16n8k32.row.col.s32.s8.s8.s32 "
                 "{%0,%1,%2,%3}, {%4,%5,%6,%7}, {%8,%9}, {%0,%1,%2,%3};"
                 : "+r"(d[0]), "+r"(d[1]), "+r"(d[2]), "+r"(d[3])
                 : "r"(a[0]), "r"(a[1]), "r"(a[2]), "r"(a[3]), "r"(b0), "r"(b1));
}
// ldmatrix fragment address: rows rowbase..+15, k32-group ks (two 16B segs)
__device__ __forceinline__ uint32_t frag_addr(uint32_t tile, int rowbase, int ks, int lane) {
    int row  = rowbase + (lane & 15);
    int cs16 = ks * 2 + (lane >> 4);
    return tile + row * BK + SWZ(row, cs16) * 16;
}

// ---------------- limbify: fp32 rows -> int8 limbs + scale ----------------
__global__ void limbify(const float* __restrict__ src, int8_t* __restrict__ l0,
                        int8_t* __restrict__ l1, float* __restrict__ rs) {
    int row = blockIdx.x;
    const float* p = src + (size_t)row * KDIM;
    int tid = threadIdx.x;
    float v[8];
    float m = 0.f;
#pragma unroll
    for (int i = 0; i < 8; i++) { v[i] = p[tid + i * 256]; m = fmaxf(m, fabsf(v[i])); }
    __shared__ float red[256];
    red[tid] = m;
    __syncthreads();
    for (int s = 128; s > 0; s >>= 1) {
        if (tid < s) red[tid] = fmaxf(red[tid], red[tid + s]);
        __syncthreads();
    }
    float mx = red[0];
    float s = (mx > 0.f) ? 127.f / mx : 0.f;
    if (tid == 0) rs[row] = (mx > 0.f) ? mx / 127.f : 0.f;
    int8_t* q0 = l0 + (size_t)row * KDIM;
    int8_t* q1 = l1 + (size_t)row * KDIM;
#pragma unroll
    for (int i = 0; i < 8; i++) {
        float as = v[i] * s;
        float a0 = rintf(as);
        float a1 = fminf(rintf((as - a0) * 256.f), 127.f);
        q0[tid + i * 256] = (int8_t)a0;
        q1[tid + i * 256] = (int8_t)a1;
    }
}

// ---------------- routing ----------------
__global__ void zero_counts_kernel() {
    if (threadIdx.x < EE) { g_cnt[threadIdx.x] = 0; g_cur[threadIdx.x] = 0; }
}

__global__ void gate_kernel(const float* __restrict__ x, const float* __restrict__ gw) {
    int t = blockIdx.x, tid = threadIdx.x;
    float acc[EE];
#pragma unroll
    for (int e = 0; e < EE; e++) acc[e] = 0.f;
    for (int h = tid; h < HH; h += 256) {
        float xv = x[(size_t)t * HH + h];
#pragma unroll
        for (int e = 0; e < EE; e++) acc[e] += xv * gw[e * HH + h];
    }
    __shared__ float red[EE][256];
#pragma unroll
    for (int e = 0; e < EE; e++) red[e][tid] = acc[e];
    __syncthreads();
    for (int s = 128; s > 0; s >>= 1) {
        if (tid < s) {
#pragma unroll
            for (int e = 0; e < EE; e++) red[e][tid] += red[e][tid + s];
        }
        __syncthreads();
    }
    if (tid == 0) {
        float lg[EE];
#pragma unroll
        for (int e = 0; e < EE; e++) lg[e] = red[e][0];
        int i1 = 0;
#pragma unroll
        for (int e = 1; e < EE; e++) if (lg[e] > lg[i1]) i1 = e;
        int i2 = -1;
#pragma unroll
        for (int e = 0; e < EE; e++)
            if (e != i1 && (i2 < 0 || lg[e] > lg[i2])) i2 = e;
        float w1 = 1.f / (1.f + expf(lg[i2] - lg[i1]));
        g_topk_idx[t * 2 + 0] = i1; g_topk_idx[t * 2 + 1] = i2;
        g_topk_w[t * 2 + 0] = w1;   g_topk_w[t * 2 + 1] = 1.f - w1;
        atomicAdd(&g_cnt[i1], 1);   atomicAdd(&g_cnt[i2], 1);
    }
}

__global__ void scan_kernel() {
    if (threadIdx.x == 0) {
        int s = 0;
        for (int e = 0; e < EE; e++) { g_off[e] = s; s += g_cnt[e]; }
    }
}

__global__ void scatter_kernel() {
    int t = blockIdx.x * blockDim.x + threadIdx.x;
    if (t >= TT) return;
#pragma unroll
    for (int k = 0; k < 2; k++) {
        int e = g_topk_idx[t * 2 + k];
        int pos = g_off[e] + atomicAdd(&g_cur[e], 1);
        g_rowtok[pos] = t;
        g_roww[pos]   = g_topk_w[t * 2 + k];
    }
}

// ---------------- int8 Ozaki-2-limb GEMM ----------------
// value = (l0 + l1/256) * rs  per row (A) / per row (B weight)
// dot = (P00 + X/256) * rsA * rsB,  P00 = sum a0*b0, X = sum (a0*b1 + a1*b0)
template <int IS_FC1>
__global__ void __launch_bounds__(512, 1) moe_gemm(
    const float* __restrict__ bias, float* __restrict__ outp)
{
    extern __shared__ char dsm[];
    __shared__ int s_row[BM];

    int e   = blockIdx.z;
    int cnt = g_cnt[e];
    int m0  = blockIdx.y * BM;
    if (m0 >= cnt) return;
    int off = g_off[e];
    int n0  = blockIdx.x * BN;
    const int NTOT = IS_FC1 ? I2 : HH;
    int tid = threadIdx.x;

    const int8_t* A0 = IS_FC1 ? g_xl0 : g_al0;
    const int8_t* A1 = IS_FC1 ? g_xl1 : g_al1;
    const int8_t* B0 = (IS_FC1 ? g_w1l0 : g_w2l0) + (size_t)e * NTOT * KDIM;
    const int8_t* B1 = (IS_FC1 ? g_w1l1 : g_w2l1) + (size_t)e * NTOT * KDIM;
    const float* rsB = (IS_FC1 ? g_w1rs : g_w2rs) + (size_t)e * NTOT;

    if (tid < BM) {
        int m = m0 + tid;
        if (IS_FC1) s_row[tid] = (m < cnt) ? g_rowtok[off + m] : g_rowtok[off];
        else        s_row[tid] = off + ((m < cnt) ? m : cnt - 1);
    }
    __syncthreads();

    uint32_t smb = s2u(dsm);

    // cp.async: 512 threads, one 16B seg per tile each: r = tid>>2 (row), cs = tid&3
    int rr = tid >> 2, cs = tid & 3;
    size_t aoff = (size_t)s_row[rr] * KDIM + cs * 16;
    size_t boff = (size_t)(n0 + rr) * KDIM + cs * 16;
    uint32_t dstoff = rr * BK + SWZ(rr, cs) * 16;

#pragma unroll
    for (int c = 0; c < NSTAGE - 1; c++) {
        uint32_t sb = smb + c * STG;
        cpasync16(sb + dstoff,             A0 + aoff + c * BK);
        cpasync16(sb + dstoff + TILEB,     A1 + aoff + c * BK);
        cpasync16(sb + dstoff + 2 * TILEB, B0 + boff + c * BK);
        cpasync16(sb + dstoff + 3 * TILEB, B1 + boff + c * BK);
        cp_commit();
    }

    int lane = tid & 31, wid = tid >> 5;
    int wm = (wid & 3) * 32;       // 4 m-warps
    int wn = (wid >> 2) * 32;      // 4 n-warps

    int acc00[2][4][4], accX[2][4][4];
#pragma unroll
    for (int i = 0; i < 2; i++)
#pragma unroll
        for (int j = 0; j < 4; j++)
#pragma unroll
            for (int k = 0; k < 4; k++) { acc00[i][j][k] = 0; accX[i][j][k] = 0; }

    int stage = 0;
    for (int c = 0; c < NCHUNK; c++) {
        cp_wait<NSTAGE - 2>();
        __syncthreads();
        // prefetch chunk c+2 into stage (c+2)%3 == (c-1)%3 (freed by the barrier)
        int cn = c + NSTAGE - 1;
        if (cn < NCHUNK) {
            uint32_t sb2 = smb + (cn % NSTAGE) * STG;
            cpasync16(sb2 + dstoff,             A0 + aoff + (size_t)cn * BK);
            cpasync16(sb2 + dstoff + TILEB,     A1 + aoff + (size_t)cn * BK);
            cpasync16(sb2 + dstoff + 2 * TILEB, B0 + boff + (size_t)cn * BK);
            cpasync16(sb2 + dstoff + 3 * TILEB, B1 + boff + (size_t)cn * BK);
        }
        cp_commit();

        uint32_t sb = smb + stage * STG;
#pragma unroll
        for (int ks = 0; ks < 2; ks++) {     // two k32 groups per BK=64
            uint32_t a0f[2][4], a1f[2][4];
#pragma unroll
            for (int mi = 0; mi < 2; mi++) {
                ldm_x4(a0f[mi], frag_addr(sb,         wm + mi * 16, ks, lane));
                ldm_x4(a1f[mi], frag_addr(sb + TILEB, wm + mi * 16, ks, lane));
            }
#pragma unroll
            for (int bq = 0; bq < 2; bq++) {
                uint32_t b0f[4], b1f[4];
                ldm_x4(b0f, frag_addr(sb + 2 * TILEB, wn + bq * 16, ks, lane));
                ldm_x4(b1f, frag_addr(sb + 3 * TILEB, wn + bq * 16, ks, lane));
#pragma unroll
                for (int mi = 0; mi < 2; mi++) {
                    mma_s8(acc00[mi][bq * 2 + 0], a0f[mi], b0f[0], b0f[2]);
                    mma_s8(accX [mi][bq * 2 + 0], a0f[mi], b1f[0], b1f[2]);
                    mma_s8(accX [mi][bq * 2 + 0], a1f[mi], b0f[0], b0f[2]);
                    mma_s8(acc00[mi][bq * 2 + 1], a0f[mi], b0f[1], b0f[3]);
                    mma_s8(accX [mi][bq * 2 + 1], a0f[mi], b1f[1], b1f[3]);
                    mma_s8(accX [mi][bq * 2 + 1], a1f[mi], b0f[1], b0f[3]);
                }
            }
        }
        stage = (stage + 1 == NSTAGE) ? 0 : stage + 1;
    }

    // -------- epilogue --------
    const float inv256 = 0.00390625f;
#pragma unroll
    for (int mi = 0; mi < 2; mi++) {
#pragma unroll
        for (int h = 0; h < 2; h++) {
            int lm = wm + mi * 16 + (lane >> 2) + h * 8;
            int m  = m0 + lm;
            if (m >= cnt) continue;
            float rsA = IS_FC1 ? g_xrs[s_row[lm]] : g_ars[s_row[lm]];
#pragma unroll
            for (int nb = 0; nb < 4; nb++) {
                int f = n0 + wn + nb * 8 + (lane & 3) * 2;
                float v0 = ((float)acc00[mi][nb][h * 2 + 0] +
                            (float)accX[mi][nb][h * 2 + 0] * inv256) * rsA * rsB[f];
                float v1 = ((float)acc00[mi][nb][h * 2 + 1] +
                            (float)accX[mi][nb][h * 2 + 1] * inv256) * rsA * rsB[f + 1];
                if (IS_FC1) {
                    float g = v0 + bias[(size_t)e * NTOT + f];
                    float l = v1 + bias[(size_t)e * NTOT + f + 1];
                    float sg = 1.f / (1.f + __expf(-1.702f * g));
                    g_actf[(size_t)(off + m) * II + (f >> 1)] = g * sg * (l + 1.f);
                } else {
                    int row = off + m;
                    int tok = g_rowtok[row];
                    float w = g_roww[row];
                    atomicAdd(&outp[(size_t)tok * HH + f],
                              w * (v0 + bias[(size_t)e * NTOT + f]));
                    atomicAdd(&outp[(size_t)tok * HH + f + 1],
                              w * (v1 + bias[(size_t)e * NTOT + f + 1]));
                }
            }
        }
    }
}

// ---------------- launch ----------------
extern "C" void kernel_launch(void* const* d_in, const int* in_sizes, int n_in,
                              void* d_out, int out_size) {
    const float* x  = (const float*)d_in[0];
    const float* gw = (const float*)d_in[1];
    const float* w1 = (const float*)d_in[2];
    const float* b1 = (const float*)d_in[3];
    const float* w2 = (const float*)d_in[4];
    const float* b2 = (const float*)d_in[5];
    float* out = (float*)d_out;

    cudaFuncSetAttribute(moe_gemm<1>, cudaFuncAttributeMaxDynamicSharedMemorySize, SMEM_DYN);
    cudaFuncSetAttribute(moe_gemm<0>, cudaFuncAttributeMaxDynamicSharedMemorySize, SMEM_DYN);

    int8_t *xl0, *xl1, *w1l0, *w1l1, *w2l0, *w2l1, *al0, *al1;
    float  *xrs, *w1rs, *w2rs, *ars, *actf;
    cudaGetSymbolAddress((void**)&xl0,  g_xl0);   cudaGetSymbolAddress((void**)&xl1,  g_xl1);
    cudaGetSymbolAddress((void**)&xrs,  g_xrs);
    cudaGetSymbolAddress((void**)&w1l0, g_w1l0);  cudaGetSymbolAddress((void**)&w1l1, g_w1l1);
    cudaGetSymbolAddress((void**)&w1rs, g_w1rs);
    cudaGetSymbolAddress((void**)&w2l0, g_w2l0);  cudaGetSymbolAddress((void**)&w2l1, g_w2l1);
    cudaGetSymbolAddress((void**)&w2rs, g_w2rs);
    cudaGetSymbolAddress((void**)&al0,  g_al0);   cudaGetSymbolAddress((void**)&al1,  g_al1);
    cudaGetSymbolAddress((void**)&ars,  g_ars);
    cudaGetSymbolAddress((void**)&actf, g_actf);

    cudaMemsetAsync(out, 0, (size_t)TT * HH * sizeof(float), 0);
    limbify<<<TT,       256>>>(x,  xl0,  xl1,  xrs);
    limbify<<<EE * I2,  256>>>(w1, w1l0, w1l1, w1rs);
    limbify<<<EE * HH,  256>>>(w2, w2l0, w2l1, w2rs);
    zero_counts_kernel<<<1, 32>>>();
    gate_kernel<<<TT, 256>>>(x, gw);
    scan_kernel<<<1, 32>>>();
    scatter_kernel<<<(TT + 255) / 256, 256>>>();
    moe_gemm<1><<<dim3(I2 / BN, NASS / BM, EE), 512, SMEM_DYN>>>(b1, nullptr);
    limbify<<<NASS, 256>>>(actf, al0, al1, ars);
    moe_gemm<0><<<dim3(HH / BN, NASS / BM, EE), 512, SMEM_DYN>>>(b2, out);
}

// round 11
// speedup vs baseline: 2.4296x; 2.4296x over previous
#include <cuda_runtime.h>
#include <cuda_bf16.h>
#include <cstdint>
#include <math.h>

// Problem constants (B=4, S=1024, H=2048, I=2048, E=8, top_k=2)
#define TT   4096
#define HH   2048
#define EE   8
#define II   2048
#define I2   4096
#define NASS (TT * 2)
#define KDIM 2048
#define BM   128
#define BN   128
#define BK   32
#define NCHUNK (KDIM / BK)   // 64
#define NSTAGE 3
#define STRD 32
#define TILEB (BM * STRD * 2)          // 8192 B
#define STG   (4 * TILEB)              // 32768 B
#define SMEM_DYN (NSTAGE * STG)        // 98304 B -> 2 CTAs/SM

// Swizzle of 16B segments within 64B rows (conflict-free ldmatrix + cp.async)
#define SWZ(r, cs) ((cs) ^ ((r) & 3))

// ---------------- scratch (device globals) ----------------
__device__ int   g_topk_idx[TT * 2];
__device__ float g_topk_w[TT * 2];
__device__ int   g_cnt[EE];
__device__ int   g_off[EE];
__device__ int   g_cur[EE];
__device__ int   g_rowtok[NASS];
__device__ float g_roww[NASS];
__device__ __nv_bfloat16 g_xhi[(size_t)TT * HH],  g_xlo[(size_t)TT * HH];
__device__ __nv_bfloat16 g_w1hi[(size_t)EE * I2 * HH], g_w1lo[(size_t)EE * I2 * HH];
__device__ __nv_bfloat16 g_w2hi[(size_t)EE * HH * II], g_w2lo[(size_t)EE * HH * II];
__device__ __nv_bfloat16 g_acthi[(size_t)NASS * II], g_actlo[(size_t)NASS * II];

// ---------------- helpers ----------------
__device__ __forceinline__ uint32_t s2u(const void* p) {
    uint32_t a;
    asm("{ .reg .u64 t; cvta.to.shared.u64 t, %1; cvt.u32.u64 %0, t; }" : "=r"(a) : "l"(p));
    return a;
}
__device__ __forceinline__ void cpasync16(uint32_t dst, const void* src) {
    asm volatile("cp.async.cg.shared.global [%0], [%1], 16;" :: "r"(dst), "l"(src));
}
__device__ __forceinline__ void cp_commit() { asm volatile("cp.async.commit_group;"); }
template <int N>
__device__ __forceinline__ void cp_wait() { asm volatile("cp.async.wait_group %0;" :: "n"(N)); }

__device__ __forceinline__ void ldm_x4(uint32_t* r, uint32_t addr) {
    asm volatile("ldmatrix.sync.aligned.m8n8.x4.shared.b16 {%0,%1,%2,%3}, [%4];"
                 : "=r"(r[0]), "=r"(r[1]), "=r"(r[2]), "=r"(r[3]) : "r"(addr));
}
__device__ __forceinline__ void mma16816(float* d, const uint32_t* a, uint32_t b0, uint32_t b1) {
    asm volatile("mma.sync.aligned.m16n8k16.row.col.f32.bf16.bf16.f32 "
                 "{%0,%1,%2,%3}, {%4,%5,%6,%7}, {%8,%9}, {%0,%1,%2,%3};"
                 : "+f"(d[0]), "+f"(d[1]), "+f"(d[2]), "+f"(d[3])
                 : "r"(a[0]), "r"(a[1]), "r"(a[2]), "r"(a[3]), "r"(b0), "r"(b1));
}
__device__ __forceinline__ uint32_t frag_addr(uint32_t tilebase, int rowbase, int ks, int lane) {
    int row  = rowbase + (lane & 15);
    int cs16 = ks * 2 + (lane >> 4);
    return tilebase + row * (STRD * 2) + SWZ(row, cs16) * 16;
}

// ---------------- split-convert ----------------
__global__ void convert_split(const float4* __restrict__ src,
                              __nv_bfloat162* __restrict__ hi2,
                              __nv_bfloat162* __restrict__ lo2, size_t n4) {
    size_t stride = (size_t)gridDim.x * blockDim.x;
    for (size_t i = (size_t)blockIdx.x * blockDim.x + threadIdx.x; i < n4; i += stride) {
        float4 v = src[i];
        __nv_bfloat16 h0 = __float2bfloat16_rn(v.x), h1 = __float2bfloat16_rn(v.y);
        __nv_bfloat16 h2 = __float2bfloat16_rn(v.z), h3 = __float2bfloat16_rn(v.w);
        hi2[i * 2 + 0] = __halves2bfloat162(h0, h1);
        hi2[i * 2 + 1] = __halves2bfloat162(h2, h3);
        lo2[i * 2 + 0] = __floats2bfloat162_rn(v.x - __bfloat162float(h0),
                                               v.y - __bfloat162float(h1));
        lo2[i * 2 + 1] = __floats2bfloat162_rn(v.z - __bfloat162float(h2),
                                               v.w - __bfloat162float(h3));
    }
}

// ---------------- routing ----------------
__global__ void zero_counts_kernel() {
    if (threadIdx.x < EE) { g_cnt[threadIdx.x] = 0; g_cur[threadIdx.x] = 0; }
}

__global__ void gate_kernel(const float* __restrict__ x, const float* __restrict__ gw) {
    int t = blockIdx.x, tid = threadIdx.x;
    float acc[EE];
#pragma unroll
    for (int e = 0; e < EE; e++) acc[e] = 0.f;
    for (int h = tid; h < HH; h += 256) {
        float xv = x[(size_t)t * HH + h];
#pragma unroll
        for (int e = 0; e < EE; e++) acc[e] += xv * gw[e * HH + h];
    }
    __shared__ float red[EE][256];
#pragma unroll
    for (int e = 0; e < EE; e++) red[e][tid] = acc[e];
    __syncthreads();
    for (int s = 128; s > 0; s >>= 1) {
        if (tid < s) {
#pragma unroll
            for (int e = 0; e < EE; e++) red[e][tid] += red[e][tid + s];
        }
        __syncthreads();
    }
    if (tid == 0) {
        float lg[EE];
#pragma unroll
        for (int e = 0; e < EE; e++) lg[e] = red[e][0];
        int i1 = 0;
#pragma unroll
        for (int e = 1; e < EE; e++) if (lg[e] > lg[i1]) i1 = e;
        int i2 = -1;
#pragma unroll
        for (int e = 0; e < EE; e++)
            if (e != i1 && (i2 < 0 || lg[e] > lg[i2])) i2 = e;
        float w1 = 1.f / (1.f + expf(lg[i2] - lg[i1]));
        g_topk_idx[t * 2 + 0] = i1; g_topk_idx[t * 2 + 1] = i2;
        g_topk_w[t * 2 + 0] = w1;   g_topk_w[t * 2 + 1] = 1.f - w1;
        atomicAdd(&g_cnt[i1], 1);   atomicAdd(&g_cnt[i2], 1);
    }
}

__global__ void scan_kernel() {
    if (threadIdx.x == 0) {
        int s = 0;
        for (int e = 0; e < EE; e++) { g_off[e] = s; s += g_cnt[e]; }
    }
}

__global__ void scatter_kernel() {
    int t = blockIdx.x * blockDim.x + threadIdx.x;
    if (t >= TT) return;
#pragma unroll
    for (int k = 0; k < 2; k++) {
        int e = g_topk_idx[t * 2 + k];
        int pos = g_off[e] + atomicAdd(&g_cur[e], 1);
        g_rowtok[pos] = t;
        g_roww[pos]   = g_topk_w[t * 2 + k];
    }
}

// ---------------- split-bf16 HMMA GEMM, cp.async 3-stage, 2 CTAs/SM ----------------
template <int IS_FC1>
__global__ void __launch_bounds__(256, 2) moe_gemm(
    const float* __restrict__ bias, float* __restrict__ outp)
{
    extern __shared__ char dsm[];
    __shared__ int s_row[BM];

    int e   = blockIdx.z;
    int cnt = g_cnt[e];
    int m0  = blockIdx.y * BM;
    if (m0 >= cnt) return;
    int off = g_off[e];
    int n0  = blockIdx.x * BN;
    const int NTOT = IS_FC1 ? I2 : HH;
    int tid = threadIdx.x;

    const __nv_bfloat16* Ahi = IS_FC1 ? g_xhi : g_acthi;
    const __nv_bfloat16* Alo = IS_FC1 ? g_xlo : g_actlo;
    const __nv_bfloat16* Bhi = (IS_FC1 ? g_w1hi : g_w2hi) + (size_t)e * NTOT * KDIM;
    const __nv_bfloat16* Blo = (IS_FC1 ? g_w1lo : g_w2lo) + (size_t)e * NTOT * KDIM;

    if (tid < BM) {
        int m = m0 + tid;
        if (IS_FC1) s_row[tid] = (m < cnt) ? g_rowtok[off + m] : g_rowtok[off];
        else        s_row[tid] = off + ((m < cnt) ? m : cnt - 1);
    }
    __syncthreads();

    uint32_t smb = s2u(dsm);

    // cp.async: idx in {tid, tid+256}; r = idx>>2, cs = idx&3 (16B segment)
    size_t aoff[2], boff[2];
    uint32_t dstoff[2];
#pragma unroll
    for (int i = 0; i < 2; i++) {
        int idx = tid + i * 256;
        int r = idx >> 2, cs = idx & 3;
        aoff[i] = (size_t)s_row[r] * KDIM + cs * 8;
        boff[i] = (size_t)(n0 + r) * KDIM + cs * 8;
        dstoff[i] = r * (STRD * 2) + SWZ(r, cs) * 16;
    }

#pragma unroll
    for (int c = 0; c < NSTAGE - 1; c++) {
        uint32_t sb = smb + c * STG;
#pragma unroll
        for (int i = 0; i < 2; i++) {
            cpasync16(sb + dstoff[i],             Ahi + aoff[i] + c * BK);
            cpasync16(sb + dstoff[i] + TILEB,     Alo + aoff[i] + c * BK);
            cpasync16(sb + dstoff[i] + 2 * TILEB, Bhi + boff[i] + c * BK);
            cpasync16(sb + dstoff[i] + 3 * TILEB, Blo + boff[i] + c * BK);
        }
        cp_commit();
    }

    int lane = tid & 31, wid = tid >> 5;
    int wm = (wid & 3) * 32;
    int wn = (wid >> 2) * 64;

    float acc[2][8][4];
#pragma unroll
    for (int i = 0; i < 2; i++)
#pragma unroll
        for (int j = 0; j < 8; j++)
#pragma unroll
            for (int k = 0; k < 4; k++) acc[i][j][k] = 0.f;

    int stage = 0, pstage = NSTAGE - 1;   // stage of chunk c, stage of chunk c+NSTAGE-1
    for (int c = 0; c < NCHUNK; c++) {
        cp_wait<NSTAGE - 2>();
        __syncthreads();
        // prefetch chunk c+2 into its stage (freed by the barrier above) BEFORE compute,
        // so the load has the entire chunk's MMA work to hide under.
        int cn = c + NSTAGE - 1;
        if (cn < NCHUNK) {
            uint32_t sb2 = smb + pstage * STG;
#pragma unroll
            for (int i = 0; i < 2; i++) {
                cpasync16(sb2 + dstoff[i],             Ahi + aoff[i] + (size_t)cn * BK);
                cpasync16(sb2 + dstoff[i] + TILEB,     Alo + aoff[i] + (size_t)cn * BK);
                cpasync16(sb2 + dstoff[i] + 2 * TILEB, Bhi + boff[i] + (size_t)cn * BK);
                cpasync16(sb2 + dstoff[i] + 3 * TILEB, Blo + boff[i] + (size_t)cn * BK);
            }
        }
        cp_commit();

        uint32_t sb = smb + stage * STG;
#pragma unroll
        for (int ks = 0; ks < 2; ks++) {
            uint32_t ah[2][4], al[2][4];
#pragma unroll
            for (int mi = 0; mi < 2; mi++) {
                ldm_x4(ah[mi], frag_addr(sb,             wm + mi * 16, ks, lane));
                ldm_x4(al[mi], frag_addr(sb + TILEB,     wm + mi * 16, ks, lane));
            }
#pragma unroll
            for (int bq = 0; bq < 4; bq++) {
                uint32_t bh[4], bl[4];
                ldm_x4(bh, frag_addr(sb + 2 * TILEB, wn + bq * 16, ks, lane));
                ldm_x4(bl, frag_addr(sb + 3 * TILEB, wn + bq * 16, ks, lane));
#pragma unroll
                for (int mi = 0; mi < 2; mi++) {
                    mma16816(acc[mi][bq * 2 + 0], ah[mi], bh[0], bh[2]);
                    mma16816(acc[mi][bq * 2 + 0], ah[mi], bl[0], bl[2]);
                    mma16816(acc[mi][bq * 2 + 0], al[mi], bh[0], bh[2]);
                    mma16816(acc[mi][bq * 2 + 1], ah[mi], bh[1], bh[3]);
                    mma16816(acc[mi][bq * 2 + 1], ah[mi], bl[1], bl[3]);
                    mma16816(acc[mi][bq * 2 + 1], al[mi], bh[1], bh[3]);
                }
            }
        }
        stage  = (stage  + 1 == NSTAGE) ? 0 : stage  + 1;
        pstage = (pstage + 1 == NSTAGE) ? 0 : pstage + 1;
    }

    // -------- epilogue --------
#pragma unroll
    for (int mi = 0; mi < 2; mi++) {
#pragma unroll
        for (int h = 0; h < 2; h++) {
            int m = m0 + wm + mi * 16 + (lane >> 2) + h * 8;
            if (m >= cnt) continue;
            if (IS_FC1) {
                size_t rowo = (size_t)(off + m) * II;
#pragma unroll
                for (int nb = 0; nb < 8; nb++) {
                    int f = n0 + wn + nb * 8 + (lane & 3) * 2;
                    float g = acc[mi][nb][h * 2 + 0] + bias[(size_t)e * NTOT + f];
                    float l = acc[mi][nb][h * 2 + 1] + bias[(size_t)e * NTOT + f + 1];
                    float sg = 1.f / (1.f + __expf(-1.702f * g));
                    float a  = g * sg * (l + 1.f);
                    __nv_bfloat16 hb = __float2bfloat16_rn(a);
                    g_acthi[rowo + (f >> 1)] = hb;
                    g_actlo[rowo + (f >> 1)] = __float2bfloat16_rn(a - __bfloat162float(hb));
                }
            } else {
                int row = off + m;
                int tok = g_rowtok[row];
                float w = g_roww[row];
                size_t o = (size_t)tok * HH;
#pragma unroll
                for (int nb = 0; nb < 8; nb++) {
                    int f = n0 + wn + nb * 8 + (lane & 3) * 2;
                    float y0 = acc[mi][nb][h * 2 + 0] + bias[(size_t)e * NTOT + f];
                    float y1 = acc[mi][nb][h * 2 + 1] + bias[(size_t)e * NTOT + f + 1];
                    atomicAdd(&outp[o + f],     w * y0);
                    atomicAdd(&outp[o + f + 1], w * y1);
                }
            }
        }
    }
}

// ---------------- launch ----------------
extern "C" void kernel_launch(void* const* d_in, const int* in_sizes, int n_in,
                              void* d_out, int out_size) {
    const float* x  = (const float*)d_in[0];
    const float* gw = (const float*)d_in[1];
    const float* w1 = (const float*)d_in[2];
    const float* b1 = (const float*)d_in[3];
    const float* w2 = (const float*)d_in[4];
    const float* b2 = (const float*)d_in[5];
    float* out = (float*)d_out;

    cudaFuncSetAttribute(moe_gemm<1>, cudaFuncAttributeMaxDynamicSharedMemorySize, SMEM_DYN);
    cudaFuncSetAttribute(moe_gemm<0>, cudaFuncAttributeMaxDynamicSharedMemorySize, SMEM_DYN);

    __nv_bfloat162 *xhi, *xlo, *w1hi, *w1lo, *w2hi, *w2lo;
    cudaGetSymbolAddress((void**)&xhi,  g_xhi);
    cudaGetSymbolAddress((void**)&xlo,  g_xlo);
    cudaGetSymbolAddress((void**)&w1hi, g_w1hi);
    cudaGetSymbolAddress((void**)&w1lo, g_w1lo);
    cudaGetSymbolAddress((void**)&w2hi, g_w2hi);
    cudaGetSymbolAddress((void**)&w2lo, g_w2lo);

    cudaMemsetAsync(out, 0, (size_t)TT * HH * sizeof(float), 0);
    convert_split<<<2048, 256>>>((const float4*)x,  xhi,  xlo,  (size_t)TT * HH / 4);
    convert_split<<<4096, 256>>>((const float4*)w1, w1hi, w1lo, (size_t)EE * I2 * HH / 4);
    convert_split<<<4096, 256>>>((const float4*)w2, w2hi, w2lo, (size_t)EE * HH * II / 4);
    zero_counts_kernel<<<1, 32>>>();
    gate_kernel<<<TT, 256>>>(x, gw);
    scan_kernel<<<1, 32>>>();
    scatter_kernel<<<(TT + 255) / 256, 256>>>();
    moe_gemm<1><<<dim3(I2 / BN, NASS / BM, EE), 256, SMEM_DYN>>>(b1, nullptr);
    moe_gemm<0><<<dim3(HH / BN, NASS / BM, EE), 256, SMEM_DYN>>>(b2, out);
}

// round 12
// speedup vs baseline: 2.4675x; 1.0156x over previous
#include <cuda_runtime.h>
#include <cuda_bf16.h>
#include <cstdint>
#include <math.h>

// Problem constants (B=4, S=1024, H=2048, I=2048, E=8, top_k=2)
#define TT   4096
#define HH   2048
#define EE   8
#define II   2048
#define I2   4096
#define NASS (TT * 2)
#define KDIM 2048
#define BM   128
#define BN   128
#define BK   32
#define NCHUNK (KDIM / BK)   // 64
#define NSTAGE 3
#define STRD 32
#define TILEB (BM * STRD * 2)          // 8192 B
#define STG   (4 * TILEB)              // 32768 B
#define SMEM_DYN (NSTAGE * STG)        // 98304 B -> 2 CTAs/SM

#define SWZ(r, cs) ((cs) ^ ((r) & 3))

// ---------------- scratch (device globals) ----------------
__device__ int   g_topk_idx[TT * 2];
__device__ float g_topk_w[TT * 2];
__device__ int   g_cnt[EE];
__device__ int   g_off[EE];
__device__ int   g_cur[EE];
__device__ int   g_rowtok[NASS];
__device__ float g_roww[NASS];
__device__ int   g_pos[TT * 2];               // inverse map: (token,k) -> assignment row
__device__ __nv_bfloat16 g_xhi[(size_t)TT * HH],  g_xlo[(size_t)TT * HH];
__device__ __nv_bfloat16 g_w1hi[(size_t)EE * I2 * HH], g_w1lo[(size_t)EE * I2 * HH];
__device__ __nv_bfloat16 g_w2hi[(size_t)EE * HH * II], g_w2lo[(size_t)EE * HH * II];
__device__ __nv_bfloat16 g_acthi[(size_t)NASS * II], g_actlo[(size_t)NASS * II];
__device__ float g_y[(size_t)NASS * HH];      // per-assignment FC2 output (64 MB)

// ---------------- helpers ----------------
__device__ __forceinline__ uint32_t s2u(const void* p) {
    uint32_t a;
    asm("{ .reg .u64 t; cvta.to.shared.u64 t, %1; cvt.u32.u64 %0, t; }" : "=r"(a) : "l"(p));
    return a;
}
__device__ __forceinline__ void cpasync16(uint32_t dst, const void* src) {
    asm volatile("cp.async.cg.shared.global [%0], [%1], 16;" :: "r"(dst), "l"(src));
}
__device__ __forceinline__ void cp_commit() { asm volatile("cp.async.commit_group;"); }
template <int N>
__device__ __forceinline__ void cp_wait() { asm volatile("cp.async.wait_group %0;" :: "n"(N)); }

__device__ __forceinline__ void ldm_x4(uint32_t* r, uint32_t addr) {
    asm volatile("ldmatrix.sync.aligned.m8n8.x4.shared.b16 {%0,%1,%2,%3}, [%4];"
                 : "=r"(r[0]), "=r"(r[1]), "=r"(r[2]), "=r"(r[3]) : "r"(addr));
}
__device__ __forceinline__ void mma16816(float* d, const uint32_t* a, uint32_t b0, uint32_t b1) {
    asm volatile("mma.sync.aligned.m16n8k16.row.col.f32.bf16.bf16.f32 "
                 "{%0,%1,%2,%3}, {%4,%5,%6,%7}, {%8,%9}, {%0,%1,%2,%3};"
                 : "+f"(d[0]), "+f"(d[1]), "+f"(d[2]), "+f"(d[3])
                 : "r"(a[0]), "r"(a[1]), "r"(a[2]), "r"(a[3]), "r"(b0), "r"(b1));
}
__device__ __forceinline__ uint32_t frag_addr(uint32_t tilebase, int rowbase, int ks, int lane) {
    int row  = rowbase + (lane & 15);
    int cs16 = ks * 2 + (lane >> 4);
    return tilebase + row * (STRD * 2) + SWZ(row, cs16) * 16;
}

// ---------------- split-convert ----------------
__global__ void convert_split(const float4* __restrict__ src,
                              __nv_bfloat162* __restrict__ hi2,
                              __nv_bfloat162* __restrict__ lo2, size_t n4) {
    size_t stride = (size_t)gridDim.x * blockDim.x;
    for (size_t i = (size_t)blockIdx.x * blockDim.x + threadIdx.x; i < n4; i += stride) {
        float4 v = src[i];
        __nv_bfloat16 h0 = __float2bfloat16_rn(v.x), h1 = __float2bfloat16_rn(v.y);
        __nv_bfloat16 h2 = __float2bfloat16_rn(v.z), h3 = __float2bfloat16_rn(v.w);
        hi2[i * 2 + 0] = __halves2bfloat162(h0, h1);
        hi2[i * 2 + 1] = __halves2bfloat162(h2, h3);
        lo2[i * 2 + 0] = __floats2bfloat162_rn(v.x - __bfloat162float(h0),
                                               v.y - __bfloat162float(h1));
        lo2[i * 2 + 1] = __floats2bfloat162_rn(v.z - __bfloat162float(h2),
                                               v.w - __bfloat162float(h3));
    }
}

// ---------------- routing ----------------
__global__ void zero_counts_kernel() {
    if (threadIdx.x < EE) { g_cnt[threadIdx.x] = 0; g_cur[threadIdx.x] = 0; }
}

__global__ void gate_kernel(const float* __restrict__ x, const float* __restrict__ gw) {
    int t = blockIdx.x, tid = threadIdx.x;
    float acc[EE];
#pragma unroll
    for (int e = 0; e < EE; e++) acc[e] = 0.f;
    for (int h = tid; h < HH; h += 256) {
        float xv = x[(size_t)t * HH + h];
#pragma unroll
        for (int e = 0; e < EE; e++) acc[e] += xv * gw[e * HH + h];
    }
    __shared__ float red[EE][256];
#pragma unroll
    for (int e = 0; e < EE; e++) red[e][tid] = acc[e];
    __syncthreads();
    for (int s = 128; s > 0; s >>= 1) {
        if (tid < s) {
#pragma unroll
            for (int e = 0; e < EE; e++) red[e][tid] += red[e][tid + s];
        }
        __syncthreads();
    }
    if (tid == 0) {
        float lg[EE];
#pragma unroll
        for (int e = 0; e < EE; e++) lg[e] = red[e][0];
        int i1 = 0;
#pragma unroll
        for (int e = 1; e < EE; e++) if (lg[e] > lg[i1]) i1 = e;
        int i2 = -1;
#pragma unroll
        for (int e = 0; e < EE; e++)
            if (e != i1 && (i2 < 0 || lg[e] > lg[i2])) i2 = e;
        float w1 = 1.f / (1.f + expf(lg[i2] - lg[i1]));
        g_topk_idx[t * 2 + 0] = i1; g_topk_idx[t * 2 + 1] = i2;
        g_topk_w[t * 2 + 0] = w1;   g_topk_w[t * 2 + 1] = 1.f - w1;
        atomicAdd(&g_cnt[i1], 1);   atomicAdd(&g_cnt[i2], 1);
    }
}

__global__ void scan_kernel() {
    if (threadIdx.x == 0) {
        int s = 0;
        for (int e = 0; e < EE; e++) { g_off[e] = s; s += g_cnt[e]; }
    }
}

__global__ void scatter_kernel() {
    int t = blockIdx.x * blockDim.x + threadIdx.x;
    if (t >= TT) return;
#pragma unroll
    for (int k = 0; k < 2; k++) {
        int e = g_topk_idx[t * 2 + k];
        int pos = g_off[e] + atomicAdd(&g_cur[e], 1);
        g_rowtok[pos] = t;
        g_roww[pos]   = g_topk_w[t * 2 + k];
        g_pos[t * 2 + k] = pos;
    }
}

// ---------------- final combine: out[t] = w0*y[p0] + w1*y[p1] ----------------
__global__ void combine_kernel(float* __restrict__ out) {
    int t = blockIdx.x, tid = threadIdx.x;
    int p0 = g_pos[t * 2 + 0], p1 = g_pos[t * 2 + 1];
    float w0 = g_topk_w[t * 2 + 0], w1 = g_topk_w[t * 2 + 1];
    const float4* y0 = (const float4*)(g_y + (size_t)p0 * HH);
    const float4* y1 = (const float4*)(g_y + (size_t)p1 * HH);
    float4* o = (float4*)(out + (size_t)t * HH);
#pragma unroll
    for (int i = 0; i < 2; i++) {
        int c = tid + i * 256;
        float4 a = y0[c], b = y1[c];
        float4 r;
        r.x = w0 * a.x + w1 * b.x;
        r.y = w0 * a.y + w1 * b.y;
        r.z = w0 * a.z + w1 * b.z;
        r.w = w0 * a.w + w1 * b.w;
        o[c] = r;
    }
}

// ---------------- split-bf16 HMMA GEMM, cp.async 3-stage, 2 CTAs/SM ----------------
// grid: (M-tiles, N-tiles, experts) — M fastest so consecutive CTAs share weight tiles
template <int IS_FC1>
__global__ void __launch_bounds__(256, 2) moe_gemm(
    const float* __restrict__ bias, float* __restrict__ outp)
{
    extern __shared__ char dsm[];
    __shared__ int s_row[BM];

    int e   = blockIdx.z;
    int cnt = g_cnt[e];
    int m0  = blockIdx.x * BM;
    if (m0 >= cnt) return;
    int off = g_off[e];
    int n0  = blockIdx.y * BN;
    const int NTOT = IS_FC1 ? I2 : HH;
    int tid = threadIdx.x;

    const __nv_bfloat16* Ahi = IS_FC1 ? g_xhi : g_acthi;
    const __nv_bfloat16* Alo = IS_FC1 ? g_xlo : g_actlo;
    const __nv_bfloat16* Bhi = (IS_FC1 ? g_w1hi : g_w2hi) + (size_t)e * NTOT * KDIM;
    const __nv_bfloat16* Blo = (IS_FC1 ? g_w1lo : g_w2lo) + (size_t)e * NTOT * KDIM;

    if (tid < BM) {
        int m = m0 + tid;
        if (IS_FC1) s_row[tid] = (m < cnt) ? g_rowtok[off + m] : g_rowtok[off];
        else        s_row[tid] = off + ((m < cnt) ? m : cnt - 1);
    }
    __syncthreads();

    uint32_t smb = s2u(dsm);

    size_t aoff[2], boff[2];
    uint32_t dstoff[2];
#pragma unroll
    for (int i = 0; i < 2; i++) {
        int idx = tid + i * 256;
        int r = idx >> 2, cs = idx & 3;
        aoff[i] = (size_t)s_row[r] * KDIM + cs * 8;
        boff[i] = (size_t)(n0 + r) * KDIM + cs * 8;
        dstoff[i] = r * (STRD * 2) + SWZ(r, cs) * 16;
    }

#pragma unroll
    for (int c = 0; c < NSTAGE - 1; c++) {
        uint32_t sb = smb + c * STG;
#pragma unroll
        for (int i = 0; i < 2; i++) {
            cpasync16(sb + dstoff[i],             Ahi + aoff[i] + c * BK);
            cpasync16(sb + dstoff[i] + TILEB,     Alo + aoff[i] + c * BK);
            cpasync16(sb + dstoff[i] + 2 * TILEB, Bhi + boff[i] + c * BK);
            cpasync16(sb + dstoff[i] + 3 * TILEB, Blo + boff[i] + c * BK);
        }
        cp_commit();
    }

    int lane = tid & 31, wid = tid >> 5;
    int wm = (wid & 3) * 32;
    int wn = (wid >> 2) * 64;

    float acc[2][8][4];
#pragma unroll
    for (int i = 0; i < 2; i++)
#pragma unroll
        for (int j = 0; j < 8; j++)
#pragma unroll
            for (int k = 0; k < 4; k++) acc[i][j][k] = 0.f;

    int stage = 0;
    for (int c = 0; c < NCHUNK; c++) {
        cp_wait<NSTAGE - 2>();
        __syncthreads();
        uint32_t sb = smb + stage * STG;
#pragma unroll
        for (int ks = 0; ks < 2; ks++) {
            uint32_t ah[2][4], al[2][4];
#pragma unroll
            for (int mi = 0; mi < 2; mi++) {
                ldm_x4(ah[mi], frag_addr(sb,             wm + mi * 16, ks, lane));
                ldm_x4(al[mi], frag_addr(sb + TILEB,     wm + mi * 16, ks, lane));
            }
#pragma unroll
            for (int bq = 0; bq < 4; bq++) {
                uint32_t bh[4], bl[4];
                ldm_x4(bh, frag_addr(sb + 2 * TILEB, wn + bq * 16, ks, lane));
                ldm_x4(bl, frag_addr(sb + 3 * TILEB, wn + bq * 16, ks, lane));
#pragma unroll
                for (int mi = 0; mi < 2; mi++) {
                    mma16816(acc[mi][bq * 2 + 0], ah[mi], bh[0], bh[2]);
                    mma16816(acc[mi][bq * 2 + 0], ah[mi], bl[0], bl[2]);
                    mma16816(acc[mi][bq * 2 + 0], al[mi], bh[0], bh[2]);
                    mma16816(acc[mi][bq * 2 + 1], ah[mi], bh[1], bh[3]);
                    mma16816(acc[mi][bq * 2 + 1], ah[mi], bl[1], bl[3]);
                    mma16816(acc[mi][bq * 2 + 1], al[mi], bh[1], bh[3]);
                }
            }
        }
        // prefetch chunk c + NSTAGE-1 (R6 placement: after compute)
        int cn = c + NSTAGE - 1;
        if (cn < NCHUNK) {
            uint32_t sb2 = smb + (cn % NSTAGE) * STG;
#pragma unroll
            for (int i = 0; i < 2; i++) {
                cpasync16(sb2 + dstoff[i],             Ahi + aoff[i] + (size_t)cn * BK);
                cpasync16(sb2 + dstoff[i] + TILEB,     Alo + aoff[i] + (size_t)cn * BK);
                cpasync16(sb2 + dstoff[i] + 2 * TILEB, Bhi + boff[i] + (size_t)cn * BK);
                cpasync16(sb2 + dstoff[i] + 3 * TILEB, Blo + boff[i] + (size_t)cn * BK);
            }
        }
        cp_commit();
        stage = (stage + 1 == NSTAGE) ? 0 : stage + 1;
    }

    // -------- epilogue --------
#pragma unroll
    for (int mi = 0; mi < 2; mi++) {
#pragma unroll
        for (int h = 0; h < 2; h++) {
            int m = m0 + wm + mi * 16 + (lane >> 2) + h * 8;
            if (m >= cnt) continue;
            if (IS_FC1) {
                size_t rowo = (size_t)(off + m) * II;
#pragma unroll
                for (int nb = 0; nb < 8; nb++) {
                    int f = n0 + wn + nb * 8 + (lane & 3) * 2;
                    float g = acc[mi][nb][h * 2 + 0] + bias[(size_t)e * NTOT + f];
                    float l = acc[mi][nb][h * 2 + 1] + bias[(size_t)e * NTOT + f + 1];
                    float sg = 1.f / (1.f + __expf(-1.702f * g));
                    float a  = g * sg * (l + 1.f);
                    __nv_bfloat16 hb = __float2bfloat16_rn(a);
                    g_acthi[rowo + (f >> 1)] = hb;
                    g_actlo[rowo + (f >> 1)] = __float2bfloat16_rn(a - __bfloat162float(hb));
                }
            } else {
                size_t rowo = (size_t)(off + m) * HH;
#pragma unroll
                for (int nb = 0; nb < 8; nb++) {
                    int f = n0 + wn + nb * 8 + (lane & 3) * 2;
                    g_y[rowo + f]     = acc[mi][nb][h * 2 + 0] + bias[(size_t)e * NTOT + f];
                    g_y[rowo + f + 1] = acc[mi][nb][h * 2 + 1] + bias[(size_t)e * NTOT + f + 1];
                }
            }
        }
    }
}

// ---------------- launch ----------------
extern "C" void kernel_launch(void* const* d_in, const int* in_sizes, int n_in,
                              void* d_out, int out_size) {
    const float* x  = (const float*)d_in[0];
    const float* gw = (const float*)d_in[1];
    const float* w1 = (const float*)d_in[2];
    const float* b1 = (const float*)d_in[3];
    const float* w2 = (const float*)d_in[4];
    const float* b2 = (const float*)d_in[5];
    float* out = (float*)d_out;

    cudaFuncSetAttribute(moe_gemm<1>, cudaFuncAttributeMaxDynamicSharedMemorySize, SMEM_DYN);
    cudaFuncSetAttribute(moe_gemm<0>, cudaFuncAttributeMaxDynamicSharedMemorySize, SMEM_DYN);

    __nv_bfloat162 *xhi, *xlo, *w1hi, *w1lo, *w2hi, *w2lo;
    cudaGetSymbolAddress((void**)&xhi,  g_xhi);
    cudaGetSymbolAddress((void**)&xlo,  g_xlo);
    cudaGetSymbolAddress((void**)&w1hi, g_w1hi);
    cudaGetSymbolAddress((void**)&w1lo, g_w1lo);
    cudaGetSymbolAddress((void**)&w2hi, g_w2hi);
    cudaGetSymbolAddress((void**)&w2lo, g_w2lo);

    convert_split<<<2048, 256>>>((const float4*)x,  xhi,  xlo,  (size_t)TT * HH / 4);
    convert_split<<<4096, 256>>>((const float4*)w1, w1hi, w1lo, (size_t)EE * I2 * HH / 4);
    convert_split<<<4096, 256>>>((const float4*)w2, w2hi, w2lo, (size_t)EE * HH * II / 4);
    zero_counts_kernel<<<1, 32>>>();
    gate_kernel<<<TT, 256>>>(x, gw);
    scan_kernel<<<1, 32>>>();
    scatter_kernel<<<(TT + 255) / 256, 256>>>();
    moe_gemm<1><<<dim3(NASS / BM, I2 / BN, EE), 256, SMEM_DYN>>>(b1, nullptr);
    moe_gemm<0><<<dim3(NASS / BM, HH / BN, EE), 256, SMEM_DYN>>>(b2, out);
    combine_kernel<<<TT, 256>>>(out);
}

// round 13
// speedup vs baseline: 3.5152x; 1.4246x over previous
#include <cuda_runtime.h>
#include <cuda_fp16.h>
#include <cstdint>
#include <math.h>

// Problem constants (B=4, S=1024, H=2048, I=2048, E=8, top_k=2)
#define TT   4096
#define HH   2048
#define EE   8
#define II   2048
#define I2   4096
#define NASS (TT * 2)
#define KDIM 2048
#define BM   128
#define BN   128
#define BK   32
#define NCHUNK (KDIM / BK)   // 64
#define NSTAGE 4
#define STRD 32
#define TILEB (BM * STRD * 2)          // 8192 B
#define STG   (3 * TILEB)              // 24576 B per stage (Ah, Al, Bh)
#define SMEM_DYN (NSTAGE * STG)        // 98304 B -> 2 CTAs/SM

#define SWZ(r, cs) ((cs) ^ ((r) & 3))

// ---------------- scratch (device globals) ----------------
__device__ int   g_topk_idx[TT * 2];
__device__ float g_topk_w[TT * 2];
__device__ int   g_cnt[EE];
__device__ int   g_off[EE];
__device__ int   g_cur[EE];
__device__ int   g_rowtok[NASS];
__device__ float g_roww[NASS];
__device__ int   g_pos[TT * 2];
__device__ __half g_xhi[(size_t)TT * HH],  g_xlo[(size_t)TT * HH];
__device__ __half g_w1h[(size_t)EE * I2 * HH];
__device__ __half g_w2h[(size_t)EE * HH * II];
__device__ __half g_acthi[(size_t)NASS * II], g_actlo[(size_t)NASS * II];
__device__ float  g_y[(size_t)NASS * HH];     // per-assignment FC2 output (64 MB)

// ---------------- helpers ----------------
__device__ __forceinline__ uint32_t s2u(const void* p) {
    uint32_t a;
    asm("{ .reg .u64 t; cvta.to.shared.u64 t, %1; cvt.u32.u64 %0, t; }" : "=r"(a) : "l"(p));
    return a;
}
__device__ __forceinline__ void cpasync16(uint32_t dst, const void* src) {
    asm volatile("cp.async.cg.shared.global [%0], [%1], 16;" :: "r"(dst), "l"(src));
}
__device__ __forceinline__ void cp_commit() { asm volatile("cp.async.commit_group;"); }
template <int N>
__device__ __forceinline__ void cp_wait() { asm volatile("cp.async.wait_group %0;" :: "n"(N)); }

__device__ __forceinline__ void ldm_x4(uint32_t* r, uint32_t addr) {
    asm volatile("ldmatrix.sync.aligned.m8n8.x4.shared.b16 {%0,%1,%2,%3}, [%4];"
                 : "=r"(r[0]), "=r"(r[1]), "=r"(r[2]), "=r"(r[3]) : "r"(addr));
}
__device__ __forceinline__ void mma16816(float* d, const uint32_t* a, uint32_t b0, uint32_t b1) {
    asm volatile("mma.sync.aligned.m16n8k16.row.col.f32.f16.f16.f32 "
                 "{%0,%1,%2,%3}, {%4,%5,%6,%7}, {%8,%9}, {%0,%1,%2,%3};"
                 : "+f"(d[0]), "+f"(d[1]), "+f"(d[2]), "+f"(d[3])
                 : "r"(a[0]), "r"(a[1]), "r"(a[2]), "r"(a[3]), "r"(b0), "r"(b1));
}
__device__ __forceinline__ uint32_t frag_addr(uint32_t tilebase, int rowbase, int ks, int lane) {
    int row  = rowbase + (lane & 15);
    int cs16 = ks * 2 + (lane >> 4);
    return tilebase + row * (STRD * 2) + SWZ(row, cs16) * 16;
}

// ---------------- converts ----------------
// A-side: fp32 -> fp16 hi + fp16 lo (lo = residual, unscaled)
__global__ void convert_split_a(const float4* __restrict__ src,
                                __half2* __restrict__ hi2,
                                __half2* __restrict__ lo2, size_t n4) {
    size_t stride = (size_t)gridDim.x * blockDim.x;
    for (size_t i = (size_t)blockIdx.x * blockDim.x + threadIdx.x; i < n4; i += stride) {
        float4 v = src[i];
        __half h0 = __float2half_rn(v.x), h1 = __float2half_rn(v.y);
        __half h2 = __float2half_rn(v.z), h3 = __float2half_rn(v.w);
        hi2[i * 2 + 0] = __halves2half2(h0, h1);
        hi2[i * 2 + 1] = __halves2half2(h2, h3);
        lo2[i * 2 + 0] = __floats2half2_rn(v.x - __half2float(h0), v.y - __half2float(h1));
        lo2[i * 2 + 1] = __floats2half2_rn(v.z - __half2float(h2), v.w - __half2float(h3));
    }
}
// B-side: fp32 -> fp16 single
__global__ void convert_h(const float4* __restrict__ src,
                          __half2* __restrict__ h2, size_t n4) {
    size_t stride = (size_t)gridDim.x * blockDim.x;
    for (size_t i = (size_t)blockIdx.x * blockDim.x + threadIdx.x; i < n4; i += stride) {
        float4 v = src[i];
        h2[i * 2 + 0] = __floats2half2_rn(v.x, v.y);
        h2[i * 2 + 1] = __floats2half2_rn(v.z, v.w);
    }
}

// ---------------- routing ----------------
__global__ void zero_counts_kernel() {
    if (threadIdx.x < EE) { g_cnt[threadIdx.x] = 0; g_cur[threadIdx.x] = 0; }
}

__global__ void gate_kernel(const float* __restrict__ x, const float* __restrict__ gw) {
    int t = blockIdx.x, tid = threadIdx.x;
    float acc[EE];
#pragma unroll
    for (int e = 0; e < EE; e++) acc[e] = 0.f;
    for (int h = tid; h < HH; h += 256) {
        float xv = x[(size_t)t * HH + h];
#pragma unroll
        for (int e = 0; e < EE; e++) acc[e] += xv * gw[e * HH + h];
    }
    __shared__ float red[EE][256];
#pragma unroll
    for (int e = 0; e < EE; e++) red[e][tid] = acc[e];
    __syncthreads();
    for (int s = 128; s > 0; s >>= 1) {
        if (tid < s) {
#pragma unroll
            for (int e = 0; e < EE; e++) red[e][tid] += red[e][tid + s];
        }
        __syncthreads();
    }
    if (tid == 0) {
        float lg[EE];
#pragma unroll
        for (int e = 0; e < EE; e++) lg[e] = red[e][0];
        int i1 = 0;
#pragma unroll
        for (int e = 1; e < EE; e++) if (lg[e] > lg[i1]) i1 = e;
        int i2 = -1;
#pragma unroll
        for (int e = 0; e < EE; e++)
            if (e != i1 && (i2 < 0 || lg[e] > lg[i2])) i2 = e;
        float w1 = 1.f / (1.f + expf(lg[i2] - lg[i1]));
        g_topk_idx[t * 2 + 0] = i1; g_topk_idx[t * 2 + 1] = i2;
        g_topk_w[t * 2 + 0] = w1;   g_topk_w[t * 2 + 1] = 1.f - w1;
        atomicAdd(&g_cnt[i1], 1);   atomicAdd(&g_cnt[i2], 1);
    }
}

__global__ void scan_kernel() {
    if (threadIdx.x == 0) {
        int s = 0;
        for (int e = 0; e < EE; e++) { g_off[e] = s; s += g_cnt[e]; }
    }
}

__global__ void scatter_kernel() {
    int t = blockIdx.x * blockDim.x + threadIdx.x;
    if (t >= TT) return;
#pragma unroll
    for (int k = 0; k < 2; k++) {
        int e = g_topk_idx[t * 2 + k];
        int pos = g_off[e] + atomicAdd(&g_cur[e], 1);
        g_rowtok[pos] = t;
        g_roww[pos]   = g_topk_w[t * 2 + k];
        g_pos[t * 2 + k] = pos;
    }
}

// ---------------- final combine: out[t] = w0*y[p0] + w1*y[p1] ----------------
__global__ void combine_kernel(float* __restrict__ out) {
    int t = blockIdx.x, tid = threadIdx.x;
    int p0 = g_pos[t * 2 + 0], p1 = g_pos[t * 2 + 1];
    float w0 = g_topk_w[t * 2 + 0], w1 = g_topk_w[t * 2 + 1];
    const float4* y0 = (const float4*)(g_y + (size_t)p0 * HH);
    const float4* y1 = (const float4*)(g_y + (size_t)p1 * HH);
    float4* o = (float4*)(out + (size_t)t * HH);
#pragma unroll
    for (int i = 0; i < 2; i++) {
        int c = tid + i * 256;
        float4 a = y0[c], b = y1[c];
        float4 r;
        r.x = w0 * a.x + w1 * b.x;
        r.y = w0 * a.y + w1 * b.y;
        r.z = w0 * a.z + w1 * b.z;
        r.w = w0 * a.w + w1 * b.w;
        o[c] = r;
    }
}

// ---------------- fp16 asymmetric-split HMMA GEMM, cp.async 4-stage, 2 CTAs/SM ----------------
// A = ah + al (fp16 limbs), B = bh (fp16). acc += ah*bh + al*bh (fp32 accum).
// IS_FC1=1: D = gather(x) @ w1^T, epilogue bias+SwiGLU -> g_acthi/lo
// IS_FC1=0: D = act @ w2^T,       epilogue bias -> g_y rows
template <int IS_FC1>
__global__ void __launch_bounds__(256, 2) moe_gemm(
    const float* __restrict__ bias, float* __restrict__ outp)
{
    extern __shared__ char dsm[];
    __shared__ int s_row[BM];

    int e   = blockIdx.z;
    int cnt = g_cnt[e];
    int m0  = blockIdx.y * BM;
    if (m0 >= cnt) return;
    int off = g_off[e];
    int n0  = blockIdx.x * BN;
    const int NTOT = IS_FC1 ? I2 : HH;
    int tid = threadIdx.x;

    const __half* Ahi = IS_FC1 ? g_xhi : g_acthi;
    const __half* Alo = IS_FC1 ? g_xlo : g_actlo;
    const __half* Bh  = (IS_FC1 ? g_w1h : g_w2h) + (size_t)e * NTOT * KDIM;

    if (tid < BM) {
        int m = m0 + tid;
        if (IS_FC1) s_row[tid] = (m < cnt) ? g_rowtok[off + m] : g_rowtok[off];
        else        s_row[tid] = off + ((m < cnt) ? m : cnt - 1);
    }
    __syncthreads();

    uint32_t smb = s2u(dsm);

    // cp.async: idx in {tid, tid+256}; r = idx>>2, cs = idx&3 (16B segment)
    size_t aoff[2], boff[2];
    uint32_t dstoff[2];
#pragma unroll
    for (int i = 0; i < 2; i++) {
        int idx = tid + i * 256;
        int r = idx >> 2, cs = idx & 3;
        aoff[i] = (size_t)s_row[r] * KDIM + cs * 8;
        boff[i] = (size_t)(n0 + r) * KDIM + cs * 8;
        dstoff[i] = r * (STRD * 2) + SWZ(r, cs) * 16;
    }

#pragma unroll
    for (int c = 0; c < NSTAGE - 1; c++) {
        uint32_t sb = smb + c * STG;
#pragma unroll
        for (int i = 0; i < 2; i++) {
            cpasync16(sb + dstoff[i],             Ahi + aoff[i] + c * BK);
            cpasync16(sb + dstoff[i] + TILEB,     Alo + aoff[i] + c * BK);
            cpasync16(sb + dstoff[i] + 2 * TILEB, Bh  + boff[i] + c * BK);
        }
        cp_commit();
    }

    int lane = tid & 31, wid = tid >> 5;
    int wm = (wid & 3) * 32;
    int wn = (wid >> 2) * 64;

    float acc[2][8][4];
#pragma unroll
    for (int i = 0; i < 2; i++)
#pragma unroll
        for (int j = 0; j < 8; j++)
#pragma unroll
            for (int k = 0; k < 4; k++) acc[i][j][k] = 0.f;

    int stage = 0;
    for (int c = 0; c < NCHUNK; c++) {
        cp_wait<NSTAGE - 2>();
        __syncthreads();
        uint32_t sb = smb + stage * STG;
#pragma unroll
        for (int ks = 0; ks < 2; ks++) {
            uint32_t ah[2][4], al[2][4];
#pragma unroll
            for (int mi = 0; mi < 2; mi++) {
                ldm_x4(ah[mi], frag_addr(sb,         wm + mi * 16, ks, lane));
                ldm_x4(al[mi], frag_addr(sb + TILEB, wm + mi * 16, ks, lane));
            }
#pragma unroll
            for (int bq = 0; bq < 4; bq++) {
                uint32_t bh[4];
                ldm_x4(bh, frag_addr(sb + 2 * TILEB, wn + bq * 16, ks, lane));
#pragma unroll
                for (int mi = 0; mi < 2; mi++) {
                    mma16816(acc[mi][bq * 2 + 0], ah[mi], bh[0], bh[2]);
                    mma16816(acc[mi][bq * 2 + 0], al[mi], bh[0], bh[2]);
                    mma16816(acc[mi][bq * 2 + 1], ah[mi], bh[1], bh[3]);
                    mma16816(acc[mi][bq * 2 + 1], al[mi], bh[1], bh[3]);
                }
            }
        }
        // prefetch chunk c + NSTAGE-1 (measured-best placement: after compute)
        int cn = c + NSTAGE - 1;
        if (cn < NCHUNK) {
            uint32_t sb2 = smb + (cn % NSTAGE) * STG;
#pragma unroll
            for (int i = 0; i < 2; i++) {
                cpasync16(sb2 + dstoff[i],             Ahi + aoff[i] + (size_t)cn * BK);
                cpasync16(sb2 + dstoff[i] + TILEB,     Alo + aoff[i] + (size_t)cn * BK);
                cpasync16(sb2 + dstoff[i] + 2 * TILEB, Bh  + boff[i] + (size_t)cn * BK);
            }
        }
        cp_commit();
        stage = (stage + 1 == NSTAGE) ? 0 : stage + 1;
    }

    // -------- epilogue --------
#pragma unroll
    for (int mi = 0; mi < 2; mi++) {
#pragma unroll
        for (int h = 0; h < 2; h++) {
            int m = m0 + wm + mi * 16 + (lane >> 2) + h * 8;
            if (m >= cnt) continue;
            if (IS_FC1) {
                size_t rowo = (size_t)(off + m) * II;
#pragma unroll
                for (int nb = 0; nb < 8; nb++) {
                    int f = n0 + wn + nb * 8 + (lane & 3) * 2;
                    float g = acc[mi][nb][h * 2 + 0] + bias[(size_t)e * NTOT + f];
                    float l = acc[mi][nb][h * 2 + 1] + bias[(size_t)e * NTOT + f + 1];
                    float sg = 1.f / (1.f + __expf(-1.702f * g));
                    float a  = g * sg * (l + 1.f);
                    __half hb = __float2half_rn(a);
                    g_acthi[rowo + (f >> 1)] = hb;
                    g_actlo[rowo + (f >> 1)] = __float2half_rn(a - __half2float(hb));
                }
            } else {
                size_t rowo = (size_t)(off + m) * HH;
#pragma unroll
                for (int nb = 0; nb < 8; nb++) {
                    int f = n0 + wn + nb * 8 + (lane & 3) * 2;
                    g_y[rowo + f]     = acc[mi][nb][h * 2 + 0] + bias[(size_t)e * NTOT + f];
                    g_y[rowo + f + 1] = acc[mi][nb][h * 2 + 1] + bias[(size_t)e * NTOT + f + 1];
                }
            }
        }
    }
}

// ---------------- launch ----------------
extern "C" void kernel_launch(void* const* d_in, const int* in_sizes, int n_in,
                              void* d_out, int out_size) {
    const float* x  = (const float*)d_in[0];
    const float* gw = (const float*)d_in[1];
    const float* w1 = (const float*)d_in[2];
    const float* b1 = (const float*)d_in[3];
    const float* w2 = (const float*)d_in[4];
    const float* b2 = (const float*)d_in[5];
    float* out = (float*)d_out;

    cudaFuncSetAttribute(moe_gemm<1>, cudaFuncAttributeMaxDynamicSharedMemorySize, SMEM_DYN);
    cudaFuncSetAttribute(moe_gemm<0>, cudaFuncAttributeMaxDynamicSharedMemorySize, SMEM_DYN);

    __half2 *xhi, *xlo, *w1h, *w2h;
    cudaGetSymbolAddress((void**)&xhi, g_xhi);
    cudaGetSymbolAddress((void**)&xlo, g_xlo);
    cudaGetSymbolAddress((void**)&w1h, g_w1h);
    cudaGetSymbolAddress((void**)&w2h, g_w2h);

    convert_split_a<<<2048, 256>>>((const float4*)x, xhi, xlo, (size_t)TT * HH / 4);
    convert_h<<<4096, 256>>>((const float4*)w1, w1h, (size_t)EE * I2 * HH / 4);
    convert_h<<<4096, 256>>>((const float4*)w2, w2h, (size_t)EE * HH * II / 4);
    zero_counts_kernel<<<1, 32>>>();
    gate_kernel<<<TT, 256>>>(x, gw);
    scan_kernel<<<1, 32>>>();
    scatter_kernel<<<(TT + 255) / 256, 256>>>();
    moe_gemm<1><<<dim3(I2 / BN, NASS / BM, EE), 256, SMEM_DYN>>>(b1, nullptr);
    moe_gemm<0><<<dim3(HH / BN, NASS / BM, EE), 256, SMEM_DYN>>>(b2, out);
    combine_kernel<<<TT, 256>>>(out);
}

// round 14
// speedup vs baseline: 4.0435x; 1.1503x over previous
#include <cuda_runtime.h>
#include <cuda_fp16.h>
#include <cstdint>
#include <math.h>

// Problem constants (B=4, S=1024, H=2048, I=2048, E=8, top_k=2)
#define TT   4096
#define HH   2048
#define EE   8
#define II   2048
#define I2   4096
#define NASS (TT * 2)
#define KDIM 2048
#define BM   128
#define BN   128
#define BK   32
#define NCHUNK (KDIM / BK)   // 64
#define NSTAGE 4
#define STRD 32
#define TILEB (BM * STRD * 2)          // 8192 B per tile

#define SWZ(r, cs) ((cs) ^ ((r) & 3))

// ---------------- scratch (device globals) ----------------
__device__ int   g_topk_idx[TT * 2];
__device__ float g_topk_w[TT * 2];
__device__ int   g_cnt[EE];
__device__ int   g_off[EE];
__device__ int   g_cur[EE];
__device__ int   g_rowtok[NASS];
__device__ float g_roww[NASS];
__device__ int   g_pos[TT * 2];
__device__ __half g_xhi[(size_t)TT * HH],  g_xlo[(size_t)TT * HH];
__device__ __half g_w1h[(size_t)EE * I2 * HH];
__device__ __half g_w2h[(size_t)EE * HH * II];
__device__ __half g_act[(size_t)NASS * II];   // single fp16 activations
__device__ float  g_y[(size_t)NASS * HH];     // per-assignment FC2 output (64 MB)

// ---------------- helpers ----------------
__device__ __forceinline__ uint32_t s2u(const void* p) {
    uint32_t a;
    asm("{ .reg .u64 t; cvta.to.shared.u64 t, %1; cvt.u32.u64 %0, t; }" : "=r"(a) : "l"(p));
    return a;
}
__device__ __forceinline__ void cpasync16(uint32_t dst, const void* src) {
    asm volatile("cp.async.cg.shared.global [%0], [%1], 16;" :: "r"(dst), "l"(src));
}
__device__ __forceinline__ void cp_commit() { asm volatile("cp.async.commit_group;"); }
template <int N>
__device__ __forceinline__ void cp_wait() { asm volatile("cp.async.wait_group %0;" :: "n"(N)); }

__device__ __forceinline__ void ldm_x4(uint32_t* r, uint32_t addr) {
    asm volatile("ldmatrix.sync.aligned.m8n8.x4.shared.b16 {%0,%1,%2,%3}, [%4];"
                 : "=r"(r[0]), "=r"(r[1]), "=r"(r[2]), "=r"(r[3]) : "r"(addr));
}
__device__ __forceinline__ void mma16816(float* d, const uint32_t* a, uint32_t b0, uint32_t b1) {
    asm volatile("mma.sync.aligned.m16n8k16.row.col.f32.f16.f16.f32 "
                 "{%0,%1,%2,%3}, {%4,%5,%6,%7}, {%8,%9}, {%0,%1,%2,%3};"
                 : "+f"(d[0]), "+f"(d[1]), "+f"(d[2]), "+f"(d[3])
                 : "r"(a[0]), "r"(a[1]), "r"(a[2]), "r"(a[3]), "r"(b0), "r"(b1));
}
__device__ __forceinline__ uint32_t frag_addr(uint32_t tilebase, int rowbase, int ks, int lane) {
    int row  = rowbase + (lane & 15);
    int cs16 = ks * 2 + (lane >> 4);
    return tilebase + row * (STRD * 2) + SWZ(row, cs16) * 16;
}

// ---------------- converts ----------------
__global__ void convert_split_a(const float4* __restrict__ src,
                                __half2* __restrict__ hi2,
                                __half2* __restrict__ lo2, size_t n4) {
    size_t stride = (size_t)gridDim.x * blockDim.x;
    for (size_t i = (size_t)blockIdx.x * blockDim.x + threadIdx.x; i < n4; i += stride) {
        float4 v = src[i];
        __half h0 = __float2half_rn(v.x), h1 = __float2half_rn(v.y);
        __half h2 = __float2half_rn(v.z), h3 = __float2half_rn(v.w);
        hi2[i * 2 + 0] = __halves2half2(h0, h1);
        hi2[i * 2 + 1] = __halves2half2(h2, h3);
        lo2[i * 2 + 0] = __floats2half2_rn(v.x - __half2float(h0), v.y - __half2float(h1));
        lo2[i * 2 + 1] = __floats2half2_rn(v.z - __half2float(h2), v.w - __half2float(h3));
    }
}
__global__ void convert_h(const float4* __restrict__ src,
                          __half2* __restrict__ h2, size_t n4) {
    size_t stride = (size_t)gridDim.x * blockDim.x;
    for (size_t i = (size_t)blockIdx.x * blockDim.x + threadIdx.x; i < n4; i += stride) {
        float4 v = src[i];
        h2[i * 2 + 0] = __floats2half2_rn(v.x, v.y);
        h2[i * 2 + 1] = __floats2half2_rn(v.z, v.w);
    }
}

// ---------------- routing ----------------
__global__ void zero_counts_kernel() {
    if (threadIdx.x < EE) { g_cnt[threadIdx.x] = 0; g_cur[threadIdx.x] = 0; }
}

__global__ void gate_kernel(const float* __restrict__ x, const float* __restrict__ gw) {
    int t = blockIdx.x, tid = threadIdx.x;
    float acc[EE];
#pragma unroll
    for (int e = 0; e < EE; e++) acc[e] = 0.f;
    for (int h = tid; h < HH; h += 256) {
        float xv = x[(size_t)t * HH + h];
#pragma unroll
        for (int e = 0; e < EE; e++) acc[e] += xv * gw[e * HH + h];
    }
    __shared__ float red[EE][256];
#pragma unroll
    for (int e = 0; e < EE; e++) red[e][tid] = acc[e];
    __syncthreads();
    for (int s = 128; s > 0; s >>= 1) {
        if (tid < s) {
#pragma unroll
            for (int e = 0; e < EE; e++) red[e][tid] += red[e][tid + s];
        }
        __syncthreads();
    }
    if (tid == 0) {
        float lg[EE];
#pragma unroll
        for (int e = 0; e < EE; e++) lg[e] = red[e][0];
        int i1 = 0;
#pragma unroll
        for (int e = 1; e < EE; e++) if (lg[e] > lg[i1]) i1 = e;
        int i2 = -1;
#pragma unroll
        for (int e = 0; e < EE; e++)
            if (e != i1 && (i2 < 0 || lg[e] > lg[i2])) i2 = e;
        float w1 = 1.f / (1.f + expf(lg[i2] - lg[i1]));
        g_topk_idx[t * 2 + 0] = i1; g_topk_idx[t * 2 + 1] = i2;
        g_topk_w[t * 2 + 0] = w1;   g_topk_w[t * 2 + 1] = 1.f - w1;
        atomicAdd(&g_cnt[i1], 1);   atomicAdd(&g_cnt[i2], 1);
    }
}

__global__ void scan_kernel() {
    if (threadIdx.x == 0) {
        int s = 0;
        for (int e = 0; e < EE; e++) { g_off[e] = s; s += g_cnt[e]; }
    }
}

__global__ void scatter_kernel() {
    int t = blockIdx.x * blockDim.x + threadIdx.x;
    if (t >= TT) return;
#pragma unroll
    for (int k = 0; k < 2; k++) {
        int e = g_topk_idx[t * 2 + k];
        int pos = g_off[e] + atomicAdd(&g_cur[e], 1);
        g_rowtok[pos] = t;
        g_roww[pos]   = g_topk_w[t * 2 + k];
        g_pos[t * 2 + k] = pos;
    }
}

// ---------------- final combine: out[t] = w0*y[p0] + w1*y[p1] ----------------
__global__ void combine_kernel(float* __restrict__ out) {
    int t = blockIdx.x, tid = threadIdx.x;
    int p0 = g_pos[t * 2 + 0], p1 = g_pos[t * 2 + 1];
    float w0 = g_topk_w[t * 2 + 0], w1 = g_topk_w[t * 2 + 1];
    const float4* y0 = (const float4*)(g_y + (size_t)p0 * HH);
    const float4* y1 = (const float4*)(g_y + (size_t)p1 * HH);
    float4* o = (float4*)(out + (size_t)t * HH);
#pragma unroll
    for (int i = 0; i < 2; i++) {
        int c = tid + i * 256;
        float4 a = y0[c], b = y1[c];
        float4 r;
        r.x = w0 * a.x + w1 * b.x;
        r.y = w0 * a.y + w1 * b.y;
        r.z = w0 * a.z + w1 * b.z;
        r.w = w0 * a.w + w1 * b.w;
        o[c] = r;
    }
}

// ---------------- fp16 HMMA GEMM, cp.async 4-stage, 2 CTAs/SM ----------------
// IS_FC1=1 (ATERMS=2): D = (ah+al) @ bh^T, epilogue bias+SwiGLU -> g_act (fp16)
// IS_FC1=0 (ATERMS=1): D = act @ bh^T,     epilogue bias -> g_y rows
template <int IS_FC1>
__global__ void __launch_bounds__(256, 2) moe_gemm(
    const float* __restrict__ bias, float* __restrict__ outp)
{
    constexpr int ATERMS = IS_FC1 ? 2 : 1;
    constexpr int STG_T  = (ATERMS + 1) * TILEB;   // stage bytes
    extern __shared__ char dsm[];
    __shared__ int s_row[BM];

    int e   = blockIdx.z;
    int cnt = g_cnt[e];
    int m0  = blockIdx.y * BM;
    if (m0 >= cnt) return;
    int off = g_off[e];
    int n0  = blockIdx.x * BN;
    const int NTOT = IS_FC1 ? I2 : HH;
    int tid = threadIdx.x;

    const __half* Ahi = IS_FC1 ? g_xhi : g_act;
    const __half* Alo = g_xlo;                      // used only when ATERMS==2
    const __half* Bh  = (IS_FC1 ? g_w1h : g_w2h) + (size_t)e * NTOT * KDIM;

    if (tid < BM) {
        int m = m0 + tid;
        if (IS_FC1) s_row[tid] = (m < cnt) ? g_rowtok[off + m] : g_rowtok[off];
        else        s_row[tid] = off + ((m < cnt) ? m : cnt - 1);
    }
    __syncthreads();

    uint32_t smb = s2u(dsm);

    size_t aoff[2], boff[2];
    uint32_t dstoff[2];
#pragma unroll
    for (int i = 0; i < 2; i++) {
        int idx = tid + i * 256;
        int r = idx >> 2, cs = idx & 3;
        aoff[i] = (size_t)s_row[r] * KDIM + cs * 8;
        boff[i] = (size_t)(n0 + r) * KDIM + cs * 8;
        dstoff[i] = r * (STRD * 2) + SWZ(r, cs) * 16;
    }

#pragma unroll
    for (int c = 0; c < NSTAGE - 1; c++) {
        uint32_t sb = smb + c * STG_T;
#pragma unroll
        for (int i = 0; i < 2; i++) {
            cpasync16(sb + dstoff[i], Ahi + aoff[i] + c * BK);
            if (ATERMS == 2) cpasync16(sb + dstoff[i] + TILEB, Alo + aoff[i] + c * BK);
            cpasync16(sb + dstoff[i] + ATERMS * TILEB, Bh + boff[i] + c * BK);
        }
        cp_commit();
    }

    int lane = tid & 31, wid = tid >> 5;
    int wm = (wid & 3) * 32;
    int wn = (wid >> 2) * 64;

    float acc[2][8][4];
#pragma unroll
    for (int i = 0; i < 2; i++)
#pragma unroll
        for (int j = 0; j < 8; j++)
#pragma unroll
            for (int k = 0; k < 4; k++) acc[i][j][k] = 0.f;

    int stage = 0;
    for (int c = 0; c < NCHUNK; c++) {
        cp_wait<NSTAGE - 2>();
        __syncthreads();
        uint32_t sb = smb + stage * STG_T;
#pragma unroll
        for (int ks = 0; ks < 2; ks++) {
            uint32_t ah[2][4], al[2][4];
#pragma unroll
            for (int mi = 0; mi < 2; mi++) {
                ldm_x4(ah[mi], frag_addr(sb, wm + mi * 16, ks, lane));
                if (ATERMS == 2)
                    ldm_x4(al[mi], frag_addr(sb + TILEB, wm + mi * 16, ks, lane));
            }
#pragma unroll
            for (int bq = 0; bq < 4; bq++) {
                uint32_t bh[4];
                ldm_x4(bh, frag_addr(sb + ATERMS * TILEB, wn + bq * 16, ks, lane));
#pragma unroll
                for (int mi = 0; mi < 2; mi++) {
                    mma16816(acc[mi][bq * 2 + 0], ah[mi], bh[0], bh[2]);
                    mma16816(acc[mi][bq * 2 + 1], ah[mi], bh[1], bh[3]);
                    if (ATERMS == 2) {
                        mma16816(acc[mi][bq * 2 + 0], al[mi], bh[0], bh[2]);
                        mma16816(acc[mi][bq * 2 + 1], al[mi], bh[1], bh[3]);
                    }
                }
            }
        }
        int cn = c + NSTAGE - 1;
        if (cn < NCHUNK) {
            uint32_t sb2 = smb + (cn % NSTAGE) * STG_T;
#pragma unroll
            for (int i = 0; i < 2; i++) {
                cpasync16(sb2 + dstoff[i], Ahi + aoff[i] + (size_t)cn * BK);
                if (ATERMS == 2) cpasync16(sb2 + dstoff[i] + TILEB, Alo + aoff[i] + (size_t)cn * BK);
                cpasync16(sb2 + dstoff[i] + ATERMS * TILEB, Bh + boff[i] + (size_t)cn * BK);
            }
        }
        cp_commit();
        stage = (stage + 1 == NSTAGE) ? 0 : stage + 1;
    }

    // -------- epilogue --------
#pragma unroll
    for (int mi = 0; mi < 2; mi++) {
#pragma unroll
        for (int h = 0; h < 2; h++) {
            int m = m0 + wm + mi * 16 + (lane >> 2) + h * 8;
            if (m >= cnt) continue;
            if (IS_FC1) {
                size_t rowo = (size_t)(off + m) * II;
#pragma unroll
                for (int nb = 0; nb < 8; nb++) {
                    int f = n0 + wn + nb * 8 + (lane & 3) * 2;
                    float g = acc[mi][nb][h * 2 + 0] + bias[(size_t)e * NTOT + f];
                    float l = acc[mi][nb][h * 2 + 1] + bias[(size_t)e * NTOT + f + 1];
                    float sg = 1.f / (1.f + __expf(-1.702f * g));
                    g_act[rowo + (f >> 1)] = __float2half_rn(g * sg * (l + 1.f));
                }
            } else {
                size_t rowo = (size_t)(off + m) * HH;
#pragma unroll
                for (int nb = 0; nb < 8; nb++) {
                    int f = n0 + wn + nb * 8 + (lane & 3) * 2;
                    g_y[rowo + f]     = acc[mi][nb][h * 2 + 0] + bias[(size_t)e * NTOT + f];
                    g_y[rowo + f + 1] = acc[mi][nb][h * 2 + 1] + bias[(size_t)e * NTOT + f + 1];
                }
            }
        }
    }
}

// ---------------- launch ----------------
extern "C" void kernel_launch(void* const* d_in, const int* in_sizes, int n_in,
                              void* d_out, int out_size) {
    const float* x  = (const float*)d_in[0];
    const float* gw = (const float*)d_in[1];
    const float* w1 = (const float*)d_in[2];
    const float* b1 = (const float*)d_in[3];
    const float* w2 = (const float*)d_in[4];
    const float* b2 = (const float*)d_in[5];
    float* out = (float*)d_out;

    cudaFuncSetAttribute(moe_gemm<1>, cudaFuncAttributeMaxDynamicSharedMemorySize,
                         NSTAGE * 3 * TILEB);
    cudaFuncSetAttribute(moe_gemm<0>, cudaFuncAttributeMaxDynamicSharedMemorySize,
                         NSTAGE * 2 * TILEB);

    __half2 *xhi, *xlo, *w1h, *w2h;
    cudaGetSymbolAddress((void**)&xhi, g_xhi);
    cudaGetSymbolAddress((void**)&xlo, g_xlo);
    cudaGetSymbolAddress((void**)&w1h, g_w1h);
    cudaGetSymbolAddress((void**)&w2h, g_w2h);

    convert_split_a<<<2048, 256>>>((const float4*)x, xhi, xlo, (size_t)TT * HH / 4);
    convert_h<<<4096, 256>>>((const float4*)w1, w1h, (size_t)EE * I2 * HH / 4);
    convert_h<<<4096, 256>>>((const float4*)w2, w2h, (size_t)EE * HH * II / 4);
    zero_counts_kernel<<<1, 32>>>();
    gate_kernel<<<TT, 256>>>(x, gw);
    scan_kernel<<<1, 32>>>();
    scatter_kernel<<<(TT + 255) / 256, 256>>>();
    moe_gemm<1><<<dim3(I2 / BN, NASS / BM, EE), 256, NSTAGE * 3 * TILEB>>>(b1, nullptr);
    moe_gemm<0><<<dim3(HH / BN, NASS / BM, EE), 256, NSTAGE * 2 * TILEB>>>(b2, out);
    combine_kernel<<<TT, 256>>>(out);
}

// round 15
// speedup vs baseline: 5.3883x; 1.3326x over previous
#include <cuda_runtime.h>
#include <cuda_fp16.h>
#include <cstdint>
#include <math.h>

// Problem constants (B=4, S=1024, H=2048, I=2048, E=8, top_k=2)
#define TT   4096
#define HH   2048
#define EE   8
#define II   2048
#define I2   4096
#define NASS (TT * 2)
#define KDIM 2048
#define BM   128
#define BN   128
#define BK   32
#define NCHUNK (KDIM / BK)   // 64
#define NSTAGE 4
#define STRD 32
#define TILEB (BM * STRD * 2)          // 8192 B per tile
#define STG_T (2 * TILEB)              // 16384 B per stage (A, B)
#define SMEM_DYN (NSTAGE * STG_T)      // 65536 B -> 2 CTAs/SM easily

#define SWZ(r, cs) ((cs) ^ ((r) & 3))

// ---------------- scratch (device globals) ----------------
__device__ int   g_topk_idx[TT * 2];
__device__ float g_topk_w[TT * 2];
__device__ int   g_cnt[EE];
__device__ int   g_off[EE];
__device__ int   g_cur[EE];
__device__ int   g_rowtok[NASS];
__device__ float g_roww[NASS];
__device__ int   g_pos[TT * 2];
__device__ __half g_xh[(size_t)TT * HH];
__device__ __half g_w1h[(size_t)EE * I2 * HH];
__device__ __half g_w2h[(size_t)EE * HH * II];
__device__ __half g_act[(size_t)NASS * II];   // fp16 activations
__device__ float  g_y[(size_t)NASS * HH];     // per-assignment FC2 output (64 MB)

// ---------------- helpers ----------------
__device__ __forceinline__ uint32_t s2u(const void* p) {
    uint32_t a;
    asm("{ .reg .u64 t; cvta.to.shared.u64 t, %1; cvt.u32.u64 %0, t; }" : "=r"(a) : "l"(p));
    return a;
}
__device__ __forceinline__ void cpasync16(uint32_t dst, const void* src) {
    asm volatile("cp.async.cg.shared.global [%0], [%1], 16;" :: "r"(dst), "l"(src));
}
__device__ __forceinline__ void cp_commit() { asm volatile("cp.async.commit_group;"); }
template <int N>
__device__ __forceinline__ void cp_wait() { asm volatile("cp.async.wait_group %0;" :: "n"(N)); }

__device__ __forceinline__ void ldm_x4(uint32_t* r, uint32_t addr) {
    asm volatile("ldmatrix.sync.aligned.m8n8.x4.shared.b16 {%0,%1,%2,%3}, [%4];"
                 : "=r"(r[0]), "=r"(r[1]), "=r"(r[2]), "=r"(r[3]) : "r"(addr));
}
__device__ __forceinline__ void mma16816(float* d, const uint32_t* a, uint32_t b0, uint32_t b1) {
    asm volatile("mma.sync.aligned.m16n8k16.row.col.f32.f16.f16.f32 "
                 "{%0,%1,%2,%3}, {%4,%5,%6,%7}, {%8,%9}, {%0,%1,%2,%3};"
                 : "+f"(d[0]), "+f"(d[1]), "+f"(d[2]), "+f"(d[3])
                 : "r"(a[0]), "r"(a[1]), "r"(a[2]), "r"(a[3]), "r"(b0), "r"(b1));
}
__device__ __forceinline__ uint32_t frag_addr(uint32_t tilebase, int rowbase, int ks, int lane) {
    int row  = rowbase + (lane & 15);
    int cs16 = ks * 2 + (lane >> 4);
    return tilebase + row * (STRD * 2) + SWZ(row, cs16) * 16;
}

// ---------------- convert: fp32 -> fp16 ----------------
__global__ void convert_h(const float4* __restrict__ src,
                          __half2* __restrict__ h2, size_t n4) {
    size_t stride = (size_t)gridDim.x * blockDim.x;
    for (size_t i = (size_t)blockIdx.x * blockDim.x + threadIdx.x; i < n4; i += stride) {
        float4 v = src[i];
        h2[i * 2 + 0] = __floats2half2_rn(v.x, v.y);
        h2[i * 2 + 1] = __floats2half2_rn(v.z, v.w);
    }
}

// ---------------- routing ----------------
__global__ void zero_counts_kernel() {
    if (threadIdx.x < EE) { g_cnt[threadIdx.x] = 0; g_cur[threadIdx.x] = 0; }
}

__global__ void gate_kernel(const float* __restrict__ x, const float* __restrict__ gw) {
    int t = blockIdx.x, tid = threadIdx.x;
    float acc[EE];
#pragma unroll
    for (int e = 0; e < EE; e++) acc[e] = 0.f;
    for (int h = tid; h < HH; h += 256) {
        float xv = x[(size_t)t * HH + h];
#pragma unroll
        for (int e = 0; e < EE; e++) acc[e] += xv * gw[e * HH + h];
    }
    __shared__ float red[EE][256];
#pragma unroll
    for (int e = 0; e < EE; e++) red[e][tid] = acc[e];
    __syncthreads();
    for (int s = 128; s > 0; s >>= 1) {
        if (tid < s) {
#pragma unroll
            for (int e = 0; e < EE; e++) red[e][tid] += red[e][tid + s];
        }
        __syncthreads();
    }
    if (tid == 0) {
        float lg[EE];
#pragma unroll
        for (int e = 0; e < EE; e++) lg[e] = red[e][0];
        int i1 = 0;
#pragma unroll
        for (int e = 1; e < EE; e++) if (lg[e] > lg[i1]) i1 = e;
        int i2 = -1;
#pragma unroll
        for (int e = 0; e < EE; e++)
            if (e != i1 && (i2 < 0 || lg[e] > lg[i2])) i2 = e;
        float w1 = 1.f / (1.f + expf(lg[i2] - lg[i1]));
        g_topk_idx[t * 2 + 0] = i1; g_topk_idx[t * 2 + 1] = i2;
        g_topk_w[t * 2 + 0] = w1;   g_topk_w[t * 2 + 1] = 1.f - w1;
        atomicAdd(&g_cnt[i1], 1);   atomicAdd(&g_cnt[i2], 1);
    }
}

__global__ void scan_kernel() {
    if (threadIdx.x == 0) {
        int s = 0;
        for (int e = 0; e < EE; e++) { g_off[e] = s; s += g_cnt[e]; }
    }
}

__global__ void scatter_kernel() {
    int t = blockIdx.x * blockDim.x + threadIdx.x;
    if (t >= TT) return;
#pragma unroll
    for (int k = 0; k < 2; k++) {
        int e = g_topk_idx[t * 2 + k];
        int pos = g_off[e] + atomicAdd(&g_cur[e], 1);
        g_rowtok[pos] = t;
        g_roww[pos]   = g_topk_w[t * 2 + k];
        g_pos[t * 2 + k] = pos;
    }
}

// ---------------- final combine: out[t] = w0*y[p0] + w1*y[p1] ----------------
__global__ void combine_kernel(float* __restrict__ out) {
    int t = blockIdx.x, tid = threadIdx.x;
    int p0 = g_pos[t * 2 + 0], p1 = g_pos[t * 2 + 1];
    float w0 = g_topk_w[t * 2 + 0], w1 = g_topk_w[t * 2 + 1];
    const float4* y0 = (const float4*)(g_y + (size_t)p0 * HH);
    const float4* y1 = (const float4*)(g_y + (size_t)p1 * HH);
    float4* o = (float4*)(out + (size_t)t * HH);
#pragma unroll
    for (int i = 0; i < 2; i++) {
        int c = tid + i * 256;
        float4 a = y0[c], b = y1[c];
        float4 r;
        r.x = w0 * a.x + w1 * b.x;
        r.y = w0 * a.y + w1 * b.y;
        r.z = w0 * a.z + w1 * b.z;
        r.w = w0 * a.w + w1 * b.w;
        o[c] = r;
    }
}

// ---------------- fp16 HMMA GEMM, cp.async 4-stage, 2 CTAs/SM ----------------
// IS_FC1=1: D = x @ w1^T (fp16), epilogue bias+SwiGLU -> g_act (fp16)
// IS_FC1=0: D = act @ w2^T,      epilogue bias -> g_y rows
template <int IS_FC1>
__global__ void __launch_bounds__(256, 2) moe_gemm(
    const float* __restrict__ bias, float* __restrict__ outp)
{
    extern __shared__ char dsm[];
    __shared__ int s_row[BM];

    int e   = blockIdx.z;
    int cnt = g_cnt[e];
    int m0  = blockIdx.y * BM;
    if (m0 >= cnt) return;
    int off = g_off[e];
    int n0  = blockIdx.x * BN;
    const int NTOT = IS_FC1 ? I2 : HH;
    int tid = threadIdx.x;

    const __half* Ah = IS_FC1 ? g_xh : g_act;
    const __half* Bh = (IS_FC1 ? g_w1h : g_w2h) + (size_t)e * NTOT * KDIM;

    if (tid < BM) {
        int m = m0 + tid;
        if (IS_FC1) s_row[tid] = (m < cnt) ? g_rowtok[off + m] : g_rowtok[off];
        else        s_row[tid] = off + ((m < cnt) ? m : cnt - 1);
    }
    __syncthreads();

    uint32_t smb = s2u(dsm);

    size_t aoff[2], boff[2];
    uint32_t dstoff[2];
#pragma unroll
    for (int i = 0; i < 2; i++) {
        int idx = tid + i * 256;
        int r = idx >> 2, cs = idx & 3;
        aoff[i] = (size_t)s_row[r] * KDIM + cs * 8;
        boff[i] = (size_t)(n0 + r) * KDIM + cs * 8;
        dstoff[i] = r * (STRD * 2) + SWZ(r, cs) * 16;
    }

#pragma unroll
    for (int c = 0; c < NSTAGE - 1; c++) {
        uint32_t sb = smb + c * STG_T;
#pragma unroll
        for (int i = 0; i < 2; i++) {
            cpasync16(sb + dstoff[i],         Ah + aoff[i] + c * BK);
            cpasync16(sb + dstoff[i] + TILEB, Bh + boff[i] + c * BK);
        }
        cp_commit();
    }

    int lane = tid & 31, wid = tid >> 5;
    int wm = (wid & 3) * 32;
    int wn = (wid >> 2) * 64;

    float acc[2][8][4];
#pragma unroll
    for (int i = 0; i < 2; i++)
#pragma unroll
        for (int j = 0; j < 8; j++)
#pragma unroll
            for (int k = 0; k < 4; k++) acc[i][j][k] = 0.f;

    int stage = 0;
    for (int c = 0; c < NCHUNK; c++) {
        cp_wait<NSTAGE - 2>();
        __syncthreads();
        uint32_t sb = smb + stage * STG_T;
#pragma unroll
        for (int ks = 0; ks < 2; ks++) {
            uint32_t ah[2][4];
#pragma unroll
            for (int mi = 0; mi < 2; mi++)
                ldm_x4(ah[mi], frag_addr(sb, wm + mi * 16, ks, lane));
#pragma unroll
            for (int bq = 0; bq < 4; bq++) {
                uint32_t bh[4];
                ldm_x4(bh, frag_addr(sb + TILEB, wn + bq * 16, ks, lane));
#pragma unroll
                for (int mi = 0; mi < 2; mi++) {
                    mma16816(acc[mi][bq * 2 + 0], ah[mi], bh[0], bh[2]);
                    mma16816(acc[mi][bq * 2 + 1], ah[mi], bh[1], bh[3]);
                }
            }
        }
        int cn = c + NSTAGE - 1;
        if (cn < NCHUNK) {
            uint32_t sb2 = smb + (cn % NSTAGE) * STG_T;
#pragma unroll
            for (int i = 0; i < 2; i++) {
                cpasync16(sb2 + dstoff[i],         Ah + aoff[i] + (size_t)cn * BK);
                cpasync16(sb2 + dstoff[i] + TILEB, Bh + boff[i] + (size_t)cn * BK);
            }
        }
        cp_commit();
        stage = (stage + 1 == NSTAGE) ? 0 : stage + 1;
    }

    // -------- epilogue --------
#pragma unroll
    for (int mi = 0; mi < 2; mi++) {
#pragma unroll
        for (int h = 0; h < 2; h++) {
            int m = m0 + wm + mi * 16 + (lane >> 2) + h * 8;
            if (m >= cnt) continue;
            if (IS_FC1) {
                size_t rowo = (size_t)(off + m) * II;
#pragma unroll
                for (int nb = 0; nb < 8; nb++) {
                    int f = n0 + wn + nb * 8 + (lane & 3) * 2;
                    float g = acc[mi][nb][h * 2 + 0] + bias[(size_t)e * NTOT + f];
                    float l = acc[mi][nb][h * 2 + 1] + bias[(size_t)e * NTOT + f + 1];
                    float sg = 1.f / (1.f + __expf(-1.702f * g));
                    g_act[rowo + (f >> 1)] = __float2half_rn(g * sg * (l + 1.f));
                }
            } else {
                size_t rowo = (size_t)(off + m) * HH;
#pragma unroll
                for (int nb = 0; nb < 8; nb++) {
                    int f = n0 + wn + nb * 8 + (lane & 3) * 2;
                    g_y[rowo + f]     = acc[mi][nb][h * 2 + 0] + bias[(size_t)e * NTOT + f];
                    g_y[rowo + f + 1] = acc[mi][nb][h * 2 + 1] + bias[(size_t)e * NTOT + f + 1];
                }
            }
        }
    }
}

// ---------------- launch ----------------
extern "C" void kernel_launch(void* const* d_in, const int* in_sizes, int n_in,
                              void* d_out, int out_size) {
    const float* x  = (const float*)d_in[0];
    const float* gw = (const float*)d_in[1];
    const float* w1 = (const float*)d_in[2];
    const float* b1 = (const float*)d_in[3];
    const float* w2 = (const float*)d_in[4];
    const float* b2 = (const float*)d_in[5];
    float* out = (float*)d_out;

    cudaFuncSetAttribute(moe_gemm<1>, cudaFuncAttributeMaxDynamicSharedMemorySize, SMEM_DYN);
    cudaFuncSetAttribute(moe_gemm<0>, cudaFuncAttributeMaxDynamicSharedMemorySize, SMEM_DYN);

    __half2 *xh, *w1h, *w2h;
    cudaGetSymbolAddress((void**)&xh,  g_xh);
    cudaGetSymbolAddress((void**)&w1h, g_w1h);
    cudaGetSymbolAddress((void**)&w2h, g_w2h);

    convert_h<<<2048, 256>>>((const float4*)x,  xh,  (size_t)TT * HH / 4);
    convert_h<<<4096, 256>>>((const float4*)w1, w1h, (size_t)EE * I2 * HH / 4);
    convert_h<<<4096, 256>>>((const float4*)w2, w2h, (size_t)EE * HH * II / 4);
    zero_counts_kernel<<<1, 32>>>();
    gate_kernel<<<TT, 256>>>(x, gw);
    scan_kernel<<<1, 32>>>();
    scatter_kernel<<<(TT + 255) / 256, 256>>>();
    moe_gemm<1><<<dim3(I2 / BN, NASS / BM, EE), 256, SMEM_DYN>>>(b1, nullptr);
    moe_gemm<0><<<dim3(HH / BN, NASS / BM, EE), 256, SMEM_DYN>>>(b2, out);
    combine_kernel<<<TT, 256>>>(out);
}